// round 14
// baseline (speedup 1.0000x reference)
#include <cuda_runtime.h>
#include <cstdint>
#include <math.h>
#include <mma.h>

using namespace nvcuda;

// ---------------- problem constants ----------------
#define BB   2
#define SS   2048
#define TT   4096          // B*S tokens
#define DD   1024
#define HH   16
#define GG   4
#define HDIM 64
#define EE   8
#define FF   4096
#define NPAIR (TT*2)

// ---------------- scratch ----------------
__device__ float g_xn [TT*DD];           // tf32-rounded
__device__ float g_q  [TT*DD];           // tf32-rounded
__device__ float g_k  [TT*GG*HDIM];      // tf32-rounded
__device__ float g_v  [TT*GG*HDIM];      // tf32-rounded
__device__ float g_o  [TT*DD];           // tf32-rounded
__device__ float g_xn2 [TT*DD];          // exact (router)
__device__ float g_xn2r[TT*DD];          // tf32-rounded (GEMM1 A)
__device__ float g_h  [(size_t)NPAIR*FF];   // tf32-rounded (gelu out)
__device__ float g_y  [(size_t)NPAIR*DD];   // exact
__device__ int   g_counts[EE];
__device__ int   g_offs[EE+1];
__device__ int   g_te [NPAIR];
__device__ int   g_tr [NPAIR];
__device__ float g_tg [NPAIR];
__device__ int   g_pair[NPAIR];
__device__ int   g_slot[NPAIR];

// ---------------- helpers ----------------
__device__ __forceinline__ float tanh_approx(float x) {
    float y;
    asm("tanh.approx.f32 %0, %1;" : "=f"(y) : "f"(x));
    return y;
}
__device__ __forceinline__ float gelu_tanh(float x) {
    const float c0 = 0.7978845608028654f;
    float x3 = x * x * x;
    float t = tanh_approx(c0 * (x + 0.044715f * x3));
    return 0.5f * x * (1.0f + t);
}

template<class Frag>
__device__ __forceinline__ void frag_to_tf32(Frag& f) {
    #pragma unroll
    for (int i = 0; i < f.num_elements; i++)
        f.x[i] = wmma::__float_to_tf32(f.x[i]);
}

__device__ __forceinline__ void cp16(void* s, const void* g) {
    unsigned int sa = (unsigned int)__cvta_generic_to_shared(s);
    asm volatile("cp.async.cg.shared.global [%0], [%1], 16;\n" :: "r"(sa), "l"(g));
}
__device__ __forceinline__ void cp16z(void* s, const void* g, bool v) {
    unsigned int sa = (unsigned int)__cvta_generic_to_shared(s);
    int sz = v ? 16 : 0;
    asm volatile("cp.async.cg.shared.global [%0], [%1], 16, %2;\n" :: "r"(sa), "l"(g), "r"(sz));
}
__device__ __forceinline__ void cp_commit() { asm volatile("cp.async.commit_group;\n"); }
template<int N> __device__ __forceinline__ void cp_wait() {
    asm volatile("cp.async.wait_group %0;\n" :: "n"(N));
}

// ---------------- LayerNorm. MODE: 0=exact, 1=rounded, 2=dual (exact + rounded copy) ----------------
template<int MODE>
__global__ void ln_kernel(const float* __restrict__ x,
                          const float* __restrict__ scale,
                          const float* __restrict__ bias,
                          float* __restrict__ out,
                          float* __restrict__ outr)
{
    __shared__ float red[8];
    int t = blockIdx.x, tid = threadIdx.x;
    const float4* xp = reinterpret_cast<const float4*>(x + (size_t)t * DD);
    float4 v = xp[tid];
    float s = v.x + v.y + v.z + v.w;
    #pragma unroll
    for (int o = 16; o; o >>= 1) s += __shfl_xor_sync(0xffffffffu, s, o);
    if ((tid & 31) == 0) red[tid >> 5] = s;
    __syncthreads();
    if (tid < 8) {
        float r = red[tid];
        #pragma unroll
        for (int o = 4; o; o >>= 1) r += __shfl_xor_sync(0xffu, r, o);
        if (tid == 0) red[0] = r;
    }
    __syncthreads();
    float mu = red[0] * (1.0f / DD);
    float d0 = v.x - mu, d1 = v.y - mu, d2 = v.z - mu, d3 = v.w - mu;
    float sq = d0*d0 + d1*d1 + d2*d2 + d3*d3;
    #pragma unroll
    for (int o = 16; o; o >>= 1) sq += __shfl_xor_sync(0xffffffffu, sq, o);
    __syncthreads();
    if ((tid & 31) == 0) red[tid >> 5] = sq;
    __syncthreads();
    if (tid < 8) {
        float r = red[tid];
        #pragma unroll
        for (int o = 4; o; o >>= 1) r += __shfl_xor_sync(0xffu, r, o);
        if (tid == 0) red[0] = r;
    }
    __syncthreads();
    float rstd = rsqrtf(red[0] * (1.0f / DD) + 1e-6f);
    float4 sc = reinterpret_cast<const float4*>(scale)[tid];
    float4 bi = reinterpret_cast<const float4*>(bias)[tid];
    float4 o4;
    o4.x = d0 * rstd * sc.x + bi.x;
    o4.y = d1 * rstd * sc.y + bi.y;
    o4.z = d2 * rstd * sc.z + bi.z;
    o4.w = d3 * rstd * sc.w + bi.w;
    if (MODE == 1) {
        o4.x = wmma::__float_to_tf32(o4.x);
        o4.y = wmma::__float_to_tf32(o4.y);
        o4.z = wmma::__float_to_tf32(o4.z);
        o4.w = wmma::__float_to_tf32(o4.w);
    }
    reinterpret_cast<float4*>(out + (size_t)t * DD)[tid] = o4;
    if (MODE == 2) {
        float4 r4;
        r4.x = wmma::__float_to_tf32(o4.x);
        r4.y = wmma::__float_to_tf32(o4.y);
        r4.z = wmma::__float_to_tf32(o4.z);
        r4.w = wmma::__float_to_tf32(o4.w);
        reinterpret_cast<float4*>(outr + (size_t)t * DD)[tid] = r4;
    }
}

// ---------------- tf32 GEMM, cp.async double-buffered, 128x128x32 (champion config) ----------------
// A operands MUST be pre-rounded to tf32 (RN). B: pre-rounded unless CVTB (in-frag RN).
#define BM 128
#define BN 128
#define BKT 32
#define ALD 40
#define BLD 136
#define GEMM_SMEM_FLOATS (2*128*ALD + 2*32*BLD + 8*256)

template<int ACT, bool RESID, bool GATHER, bool SEG, bool QKV, bool ROUT, bool CVTB>
__global__ __launch_bounds__(256, 2)
void gemm_tc(const float* __restrict__ A,
             const float* __restrict__ Bmat,
             const float* __restrict__ biasp,
             const float* __restrict__ resid,
             float* __restrict__ C,
             int M, int N, int Kd,
             const int* __restrict__ gather,
             const int* __restrict__ counts,
             const int* __restrict__ offs,
             size_t strideB, size_t strideBias,
             const float* __restrict__ B2, const float* __restrict__ bias2, float* __restrict__ C2,
             const float* __restrict__ B3, const float* __restrict__ bias3, float* __restrict__ C3)
{
    extern __shared__ float smem[];
    float* As    = smem;                       // [2][128][ALD]
    float* Bs    = As + 2 * 128 * ALD;         // [2][32][BLD]
    float* stage = Bs + 2 * 32 * BLD;          // [8][256]

    int off = 0, Mseg = M, Nn = N, bn;
    const float* Bm = Bmat;
    const float* bias = biasp;
    float* Cout = C;
    if (QKV) {
        int xb = blockIdx.x;
        if (xb < 8)       { bn = xb * 128; }
        else if (xb < 10) { Bm = B2; bias = bias2; Cout = C2; Nn = 256; bn = (xb - 8) * 128; }
        else              { Bm = B3; bias = bias3; Cout = C3; Nn = 256; bn = (xb - 10) * 128; }
    } else {
        bn = blockIdx.x * BN;
    }
    if (SEG) {
        int e = blockIdx.z;
        Mseg = counts[e];
        off  = offs[e];
        Bm   = Bmat + (size_t)e * strideB;
        bias = biasp + (size_t)e * strideBias;
    }
    int bm = blockIdx.y * BM;
    if (bm >= Mseg) return;

    int tid  = threadIdx.x;
    int wid  = tid >> 5;
    int lane = tid & 31;
    int wm   = wid & 3;
    int wn   = wid >> 2;

    int arow = tid >> 3;            // 0..31
    int acol = (tid & 7) * 4;       // 0..28
    const float* aptr[4];
    bool aok[4];
    #pragma unroll
    for (int p = 0; p < 4; p++) {
        int grow = bm + arow + p * 32;
        aok[p] = grow < Mseg;
        long src = 0;
        if (aok[p]) src = GATHER ? (long)gather[off + grow] : (long)(off + grow);
        aptr[p] = A + (size_t)src * Kd + acol;
    }
    int brow = tid >> 3;
    int bcol = (tid & 7) * 4;
    const float* bptr = Bm + (size_t)brow * Nn + bn + bcol;

    wmma::fragment<wmma::accumulator, 16, 16, 8, float> acc[2][4];
    #pragma unroll
    for (int i = 0; i < 2; i++)
        #pragma unroll
        for (int j = 0; j < 4; j++) wmma::fill_fragment(acc[i][j], 0.0f);

    int nk = Kd / BKT;

    {
        #pragma unroll
        for (int p = 0; p < 4; p++)
            cp16z(&As[(0 * 128 + arow + p * 32) * ALD + acol], aptr[p], aok[p]);
        #pragma unroll
        for (int p = 0; p < 4; p++)
            cp16(&Bs[(0 * 32 + brow) * BLD + bcol + p * 32], bptr + p * 32);
        cp_commit();
    }

    for (int it = 0; it < nk; it++) {
        int buf = it & 1;
        if (it + 1 < nk) {
            int k0 = (it + 1) * BKT;
            int nb = buf ^ 1;
            #pragma unroll
            for (int p = 0; p < 4; p++)
                cp16z(&As[(nb * 128 + arow + p * 32) * ALD + acol], aptr[p] + k0, aok[p]);
            #pragma unroll
            for (int p = 0; p < 4; p++)
                cp16(&Bs[(nb * 32 + brow) * BLD + bcol + p * 32],
                     bptr + (size_t)k0 * Nn + p * 32);
        }
        cp_commit();
        cp_wait<1>();
        __syncthreads();

        #pragma unroll
        for (int kk = 0; kk < BKT / 8; kk++) {
            wmma::fragment<wmma::matrix_a, 16, 16, 8, wmma::precision::tf32, wmma::row_major> af[2];
            wmma::fragment<wmma::matrix_b, 16, 16, 8, wmma::precision::tf32, wmma::row_major> bf[4];
            #pragma unroll
            for (int i = 0; i < 2; i++)
                wmma::load_matrix_sync(af[i], &As[(buf * 128 + wm * 32 + i * 16) * ALD + kk * 8], ALD);
            #pragma unroll
            for (int j = 0; j < 4; j++) {
                wmma::load_matrix_sync(bf[j], &Bs[(buf * 32 + kk * 8) * BLD + wn * 64 + j * 16], BLD);
                if (CVTB) frag_to_tf32(bf[j]);
            }
            #pragma unroll
            for (int i = 0; i < 2; i++)
                #pragma unroll
                for (int j = 0; j < 4; j++)
                    wmma::mma_sync(acc[i][j], af[i], bf[j], acc[i][j]);
        }
        __syncthreads();
    }

    int er  = lane >> 1;
    int ec0 = (lane & 1) * 8;
    #pragma unroll
    for (int i = 0; i < 2; i++) {
        #pragma unroll
        for (int j = 0; j < 4; j++) {
            wmma::store_matrix_sync(&stage[wid * 256], acc[i][j], 16, wmma::mem_row_major);
            __syncwarp();
            int grow = bm + wm * 32 + i * 16 + er;
            if (grow < Mseg) {
                int gcol = bn + wn * 64 + j * 16 + ec0;
                size_t cidx = (size_t)(off + grow) * Nn + gcol;
                float v[8];
                #pragma unroll
                for (int q = 0; q < 4; q++) {
                    v[q]     = stage[wid * 256 + er * 16 + ec0 + q]     + bias[gcol + q];
                    v[q + 4] = stage[wid * 256 + er * 16 + ec0 + 4 + q] + bias[gcol + 4 + q];
                }
                if (ACT == 1) {
                    #pragma unroll
                    for (int q = 0; q < 8; q++) v[q] = gelu_tanh(v[q]);
                }
                if (RESID) {
                    float4 r0 = *reinterpret_cast<const float4*>(&resid[cidx]);
                    float4 r1 = *reinterpret_cast<const float4*>(&resid[cidx + 4]);
                    v[0] += r0.x; v[1] += r0.y; v[2] += r0.z; v[3] += r0.w;
                    v[4] += r1.x; v[5] += r1.y; v[6] += r1.z; v[7] += r1.w;
                }
                if (ROUT) {
                    #pragma unroll
                    for (int q = 0; q < 8; q++) v[q] = wmma::__float_to_tf32(v[q]);
                }
                *reinterpret_cast<float4*>(&Cout[cidx])     = make_float4(v[0], v[1], v[2], v[3]);
                *reinterpret_cast<float4*>(&Cout[cidx + 4]) = make_float4(v[4], v[5], v[6], v[7]);
            }
            __syncwarp();
        }
    }
}

// ---------------- attention: tf32 wmma flash, 64q x 64k, K/V prefetch overlap ----------------
#define APD 68
#define ATTN_SMEM_FLOATS (6*64*APD + 3*64)

__global__ __launch_bounds__(256, 2)
void attn_tc(const float* __restrict__ qb,
             const float* __restrict__ kb,
             const float* __restrict__ vb,
             const float* __restrict__ deltas,
             const float* __restrict__ time_decay,
             float* __restrict__ ob)
{
    extern __shared__ float sm[];
    float* qs  = sm;
    float* ks  = qs  + 64 * APD;
    float* vs  = ks  + 64 * APD;          // 2 buffers
    float* ps  = vs  + 2 * 64 * APD;
    float* os  = ps  + 64 * APD;
    float* dq_s = os + 64 * APD;
    float* dk_s = dq_s + 64;
    float* l_s  = dk_s + 64;

    int qt = blockIdx.x, h = blockIdx.y, b = blockIdx.z;
    int g = h >> 2;
    int tid = threadIdx.x;
    int wid = tid >> 5;
    float td = time_decay[h];
    float lam = (td > 20.f) ? td : log1pf(__expf(td));
    int q0 = qt * 64;

    {
        #pragma unroll
        for (int p = 0; p < 4; p++) {
            int ch = tid + p * 256;
            int r = ch >> 4, cc = (ch & 15) * 4;
            cp16(&qs[r * APD + cc],
                 qb + ((size_t)(b * SS + q0 + r)) * DD + h * HDIM + cc);
            size_t base = ((size_t)(b * SS + r)) * (GG * HDIM) + g * HDIM + cc;
            cp16(&ks[r * APD + cc], kb + base);
            cp16(&vs[r * APD + cc], vb + base);
        }
        cp_commit();
    }
    if (tid < 64) dq_s[tid] = deltas[b * SS + q0 + tid];
    #pragma unroll
    for (int p = 0; p < 16; p++) {
        int idx = tid + p * 256;
        os[(idx >> 6) * APD + (idx & 63)] = 0.f;
    }

    const float scale = 0.125f;
    int rw = wid & 3;
    int cw = wid >> 2;
    int prow = tid >> 2, psub = tid & 3;
    float m_prev = -INFINITY, l_run = 0.f;
    const int NT = SS / 64;

    for (int kt = 0; kt < NT; kt++) {
        int vbuf = kt & 1;
        if (tid < 64) dk_s[tid] = deltas[b * SS + kt * 64 + tid];
        cp_wait<0>();
        __syncthreads();

        // S = Q @ K^T
        {
            wmma::fragment<wmma::accumulator, 16, 16, 8, float> sacc[2];
            wmma::fill_fragment(sacc[0], 0.f);
            wmma::fill_fragment(sacc[1], 0.f);
            #pragma unroll
            for (int kk = 0; kk < 8; kk++) {
                wmma::fragment<wmma::matrix_a, 16, 16, 8, wmma::precision::tf32, wmma::row_major> af;
                wmma::fragment<wmma::matrix_b, 16, 16, 8, wmma::precision::tf32, wmma::col_major> bf[2];
                wmma::load_matrix_sync(af, &qs[(rw * 16) * APD + kk * 8], APD);
                #pragma unroll
                for (int j = 0; j < 2; j++)
                    wmma::load_matrix_sync(bf[j], &ks[(cw * 32 + j * 16) * APD + kk * 8], APD);
                #pragma unroll
                for (int j = 0; j < 2; j++)
                    wmma::mma_sync(sacc[j], af, bf[j], sacc[j]);
            }
            #pragma unroll
            for (int j = 0; j < 2; j++)
                wmma::store_matrix_sync(&ps[(rw * 16) * APD + cw * 32 + j * 16],
                                        sacc[j], APD, wmma::mem_row_major);
        }
        __syncthreads();

        // prefetch K/V[kt+1] (overlaps softmax + PV)
        if (kt + 1 < NT) {
            #pragma unroll
            for (int p = 0; p < 4; p++) {
                int ch = tid + p * 256;
                int r = ch >> 4, cc = (ch & 15) * 4;
                size_t base = ((size_t)(b * SS + (kt + 1) * 64 + r)) * (GG * HDIM) + g * HDIM + cc;
                cp16(&ks[r * APD + cc], kb + base);
                cp16(&vs[(vbuf ^ 1) * 64 * APD + r * APD + cc], vb + base);
            }
        }
        cp_commit();

        // softmax + alpha-scale of os rows
        {
            float dqv = dq_s[prow];
            float sv[16];
            float mt = -INFINITY;
            #pragma unroll
            for (int j = 0; j < 16; j++) {
                int c = psub * 16 + j;
                float s = ps[prow * APD + c] * scale - lam * fabsf(dqv - dk_s[c]);
                sv[j] = s;
                mt = fmaxf(mt, s);
            }
            mt = fmaxf(mt, __shfl_xor_sync(0xffffffffu, mt, 1));
            mt = fmaxf(mt, __shfl_xor_sync(0xffffffffu, mt, 2));
            float m_new = fmaxf(m_prev, mt);
            float alpha = __expf(m_prev - m_new);
            float sum = 0.f;
            #pragma unroll
            for (int j = 0; j < 16; j++) {
                float p = __expf(sv[j] - m_new);
                ps[prow * APD + psub * 16 + j] = p;
                sum += p;
            }
            sum += __shfl_xor_sync(0xffffffffu, sum, 1);
            sum += __shfl_xor_sync(0xffffffffu, sum, 2);
            l_run = l_run * alpha + sum;
            m_prev = m_new;
            #pragma unroll
            for (int j = 0; j < 16; j++)
                os[prow * APD + psub * 16 + j] *= alpha;
        }
        __syncthreads();

        // os += P @ V[vbuf]
        {
            wmma::fragment<wmma::accumulator, 16, 16, 8, float> pacc[2];
            #pragma unroll
            for (int j = 0; j < 2; j++)
                wmma::load_matrix_sync(pacc[j], &os[(rw * 16) * APD + cw * 32 + j * 16],
                                       APD, wmma::mem_row_major);
            #pragma unroll
            for (int kk = 0; kk < 8; kk++) {
                wmma::fragment<wmma::matrix_a, 16, 16, 8, wmma::precision::tf32, wmma::row_major> af;
                wmma::fragment<wmma::matrix_b, 16, 16, 8, wmma::precision::tf32, wmma::row_major> bf[2];
                wmma::load_matrix_sync(af, &ps[(rw * 16) * APD + kk * 8], APD);
                frag_to_tf32(af);
                #pragma unroll
                for (int j = 0; j < 2; j++)
                    wmma::load_matrix_sync(bf[j], &vs[vbuf * 64 * APD + (kk * 8) * APD + cw * 32 + j * 16], APD);
                #pragma unroll
                for (int j = 0; j < 2; j++)
                    wmma::mma_sync(pacc[j], af, bf[j], pacc[j]);
            }
            #pragma unroll
            for (int j = 0; j < 2; j++)
                wmma::store_matrix_sync(&os[(rw * 16) * APD + cw * 32 + j * 16],
                                        pacc[j], APD, wmma::mem_row_major);
        }
    }
    __syncthreads();
    if (psub == 0) l_s[prow] = l_run;
    __syncthreads();
    #pragma unroll
    for (int p = 0; p < 16; p++) {
        int idx = tid + p * 256;
        int r = idx >> 6, c = idx & 63;
        ob[((size_t)(b * SS + q0 + r)) * DD + h * HDIM + c] =
            wmma::__float_to_tf32(os[r * APD + c] / l_s[r]);
    }
}

// ---------------- router + bucketing ----------------
__global__ void zero_kernel(int* counts) {
    if (threadIdx.x < EE) counts[threadIdx.x] = 0;
}

__global__ void router_kernel(const float* __restrict__ xn2,
                              const float* __restrict__ rw,
                              const float* __restrict__ rb,
                              int* __restrict__ counts,
                              int* __restrict__ te,
                              int* __restrict__ tr,
                              float* __restrict__ tg)
{
    __shared__ float lg[EE];
    int t = blockIdx.x, tid = threadIdx.x;
    int w = tid >> 5, lane = tid & 31;
    const float* xr = xn2 + (size_t)t * DD;
    float p = 0.f;
    for (int d = lane; d < DD; d += 32)
        p += xr[d] * rw[d * EE + w];
    #pragma unroll
    for (int o = 16; o; o >>= 1) p += __shfl_xor_sync(0xffffffffu, p, o);
    if (lane == 0) lg[w] = p + rb[w];
    __syncthreads();
    if (tid == 0) {
        float best = -INFINITY, second = -INFINITY;
        int i0 = 0, i1 = 0;
        #pragma unroll
        for (int e = 0; e < EE; e++) {
            float v = lg[e];
            if (v > best)        { second = best; i1 = i0; best = v; i0 = e; }
            else if (v > second) { second = v; i1 = e; }
        }
        float g0 = 1.0f / (1.0f + expf(second - best));
        float g1 = 1.0f - g0;
        int r0 = atomicAdd(&counts[i0], 1);
        int r1 = atomicAdd(&counts[i1], 1);
        te[t * 2 + 0] = i0; te[t * 2 + 1] = i1;
        tr[t * 2 + 0] = r0; tr[t * 2 + 1] = r1;
        tg[t * 2 + 0] = g0; tg[t * 2 + 1] = g1;
    }
}

__global__ void offs_kernel(const int* __restrict__ counts, int* __restrict__ offs) {
    if (threadIdx.x == 0 && blockIdx.x == 0) {
        int acc = 0;
        for (int e = 0; e < EE; e++) { offs[e] = acc; acc += counts[e]; }
        offs[EE] = acc;
    }
}

__global__ void pack_kernel(const int* __restrict__ te, const int* __restrict__ tr,
                            const int* __restrict__ offs,
                            int* __restrict__ pair, int* __restrict__ slot)
{
    int t = blockIdx.x * blockDim.x + threadIdx.x;
    if (t >= TT) return;
    #pragma unroll
    for (int k2 = 0; k2 < 2; k2++) {
        int e = te[t * 2 + k2];
        int s = offs[e] + tr[t * 2 + k2];
        pair[s] = t;
        slot[t * 2 + k2] = s;
    }
}

__global__ void combine_kernel(const int* __restrict__ slot,
                               const float* __restrict__ tg,
                               const float* __restrict__ ybuf,
                               float* __restrict__ out)
{
    int t = blockIdx.x, tid = threadIdx.x;
    int s0 = slot[t * 2], s1 = slot[t * 2 + 1];
    float g0 = tg[t * 2], g1 = tg[t * 2 + 1];
    const float4* y0 = reinterpret_cast<const float4*>(ybuf + (size_t)s0 * DD);
    const float4* y1 = reinterpret_cast<const float4*>(ybuf + (size_t)s1 * DD);
    float4* op = reinterpret_cast<float4*>(out + (size_t)t * DD);
    float4 a = op[tid], b0 = y0[tid], b1 = y1[tid];
    a.x += g0 * b0.x + g1 * b1.x;
    a.y += g0 * b0.y + g1 * b1.y;
    a.z += g0 * b0.z + g1 * b1.z;
    a.w += g0 * b0.w + g1 * b1.w;
    op[tid] = a;
}

// ---------------- launch ----------------
extern "C" void kernel_launch(void* const* d_in, const int* in_sizes, int n_in,
                              void* d_out, int out_size)
{
    const float* x      = (const float*)d_in[0];
    const float* deltas = (const float*)d_in[1];
    const float* ln1_s  = (const float*)d_in[2];
    const float* ln1_b  = (const float*)d_in[3];
    const float* wq     = (const float*)d_in[4];
    const float* bq     = (const float*)d_in[5];
    const float* wk     = (const float*)d_in[6];
    const float* bk     = (const float*)d_in[7];
    const float* wv     = (const float*)d_in[8];
    const float* bv     = (const float*)d_in[9];
    const float* wo     = (const float*)d_in[10];
    const float* bo     = (const float*)d_in[11];
    const float* tdcy   = (const float*)d_in[12];
    const float* ln2_s  = (const float*)d_in[13];
    const float* ln2_b  = (const float*)d_in[14];
    const float* rw     = (const float*)d_in[15];
    const float* rb     = (const float*)d_in[16];
    const float* w1     = (const float*)d_in[17];
    const float* b1     = (const float*)d_in[18];
    const float* w2     = (const float*)d_in[19];
    const float* b2     = (const float*)d_in[20];
    float* out = (float*)d_out;

    float *p_xn, *p_q, *p_k, *p_v, *p_o, *p_xn2, *p_xn2r, *p_h, *p_y, *p_tg;
    int *p_counts, *p_offs, *p_te, *p_tr, *p_pair, *p_slot;
    cudaGetSymbolAddress((void**)&p_xn,  g_xn);
    cudaGetSymbolAddress((void**)&p_q,   g_q);
    cudaGetSymbolAddress((void**)&p_k,   g_k);
    cudaGetSymbolAddress((void**)&p_v,   g_v);
    cudaGetSymbolAddress((void**)&p_o,   g_o);
    cudaGetSymbolAddress((void**)&p_xn2, g_xn2);
    cudaGetSymbolAddress((void**)&p_xn2r, g_xn2r);
    cudaGetSymbolAddress((void**)&p_h,   g_h);
    cudaGetSymbolAddress((void**)&p_y,   g_y);
    cudaGetSymbolAddress((void**)&p_counts, g_counts);
    cudaGetSymbolAddress((void**)&p_offs,   g_offs);
    cudaGetSymbolAddress((void**)&p_te,     g_te);
    cudaGetSymbolAddress((void**)&p_tr,     g_tr);
    cudaGetSymbolAddress((void**)&p_tg,     g_tg);
    cudaGetSymbolAddress((void**)&p_pair,   g_pair);
    cudaGetSymbolAddress((void**)&p_slot,   g_slot);

    const int GEMM_SMEM = GEMM_SMEM_FLOATS * (int)sizeof(float);
    const int ATTN_SMEM = ATTN_SMEM_FLOATS * (int)sizeof(float);
    static bool attr_done = false;
    if (!attr_done) {
        cudaFuncSetAttribute(gemm_tc<0, false, false, false, true,  true,  true >,
                             cudaFuncAttributeMaxDynamicSharedMemorySize, GEMM_SMEM);
        cudaFuncSetAttribute(gemm_tc<0, true,  false, false, false, false, true >,
                             cudaFuncAttributeMaxDynamicSharedMemorySize, GEMM_SMEM);
        cudaFuncSetAttribute(gemm_tc<1, false, true,  true,  false, true,  true >,
                             cudaFuncAttributeMaxDynamicSharedMemorySize, GEMM_SMEM);
        cudaFuncSetAttribute(gemm_tc<0, false, false, true,  false, false, true >,
                             cudaFuncAttributeMaxDynamicSharedMemorySize, GEMM_SMEM);
        cudaFuncSetAttribute(attn_tc,
                             cudaFuncAttributeMaxDynamicSharedMemorySize, ATTN_SMEM);
        attr_done = true;
    }

    // 0) LN1 (rounded output: feeds QKV GEMM only)
    ln_kernel<1><<<TT, 256>>>(x, ln1_s, ln1_b, p_xn, nullptr);
    // 1) fused Q/K/V projection (raw weights, in-frag B CVT; outputs rounded)
    gemm_tc<0, false, false, false, true, true, true><<<dim3(12, TT / BM, 1), 256, GEMM_SMEM>>>(
        p_xn, wq, bq, nullptr, p_q, TT, DD, DD, nullptr, nullptr, nullptr, 0, 0,
        wk, bk, p_k, wv, bv, p_v);
    // 2) attention (output rounded for O-proj)
    attn_tc<<<dim3(SS / 64, HH, BB), 256, ATTN_SMEM>>>(p_q, p_k, p_v, deltas, tdcy, p_o);
    // 3) output projection + residual (raw wo, in-frag CVT; exact out)
    gemm_tc<0, true, false, false, false, false, true><<<dim3(DD / BN, TT / BM, 1), 256, GEMM_SMEM>>>(
        p_o, wo, bo, x, out, TT, DD, DD, nullptr, nullptr, nullptr, 0, 0,
        nullptr, nullptr, nullptr, nullptr, nullptr, nullptr);
    // 4) LN2 dual: exact (router) + rounded (GEMM1 A)
    ln_kernel<2><<<TT, 256>>>(out, ln2_s, ln2_b, p_xn2, p_xn2r);
    // 5) router + bucketing
    zero_kernel<<<1, 32>>>(p_counts);
    router_kernel<<<TT, 256>>>(p_xn2, rw, rb, p_counts, p_te, p_tr, p_tg);
    offs_kernel<<<1, 1>>>(p_counts, p_offs);
    pack_kernel<<<TT / 256, 256>>>(p_te, p_tr, p_offs, p_pair, p_slot);
    // 6) expert GEMM1 (gathered, HW-tanh gelu, rounded h out; w1 raw, in-frag CVT)
    gemm_tc<1, false, true, true, false, true, true><<<dim3(FF / BN, NPAIR / BM, EE), 256, GEMM_SMEM>>>(
        p_xn2r, w1, b1, nullptr, p_h, 0, FF, DD, p_pair, p_counts, p_offs,
        (size_t)DD * FF, (size_t)FF,
        nullptr, nullptr, nullptr, nullptr, nullptr, nullptr);
    // 7) expert GEMM2 (exact y out; w2 raw, in-frag CVT)
    gemm_tc<0, false, false, true, false, false, true><<<dim3(DD / BN, NPAIR / BM, EE), 256, GEMM_SMEM>>>(
        p_h, w2, b2, nullptr, p_y, 0, DD, FF, nullptr, p_counts, p_offs,
        (size_t)FF * DD, (size_t)DD,
        nullptr, nullptr, nullptr, nullptr, nullptr, nullptr);
    // 8) combine
    combine_kernel<<<TT, 256>>>(p_slot, p_tg, p_y, out);

    (void)in_sizes; (void)n_in; (void)out_size;
}

// round 15
// speedup vs baseline: 1.0029x; 1.0029x over previous
#include <cuda_runtime.h>
#include <cstdint>
#include <math.h>
#include <mma.h>

using namespace nvcuda;

// ---------------- problem constants ----------------
#define BB   2
#define SS   2048
#define TT   4096          // B*S tokens
#define DD   1024
#define HH   16
#define GG   4
#define HDIM 64
#define EE   8
#define FF   4096
#define NPAIR (TT*2)

// ---------------- scratch ----------------
__device__ float g_xn [TT*DD];           // tf32-rounded
__device__ float g_q  [TT*DD];           // tf32-rounded
__device__ float g_k  [TT*GG*HDIM];      // tf32-rounded
__device__ float g_v  [TT*GG*HDIM];      // tf32-rounded
__device__ float g_o  [TT*DD];           // tf32-rounded
__device__ float g_xn2 [TT*DD];          // exact (router)
__device__ float g_xn2r[TT*DD];          // tf32-rounded (GEMM1 A)
__device__ float g_h  [(size_t)NPAIR*FF];   // tf32-rounded (gelu out)
__device__ float g_y  [(size_t)NPAIR*DD];   // exact
__device__ float g_wqr[DD*DD];
__device__ float g_wkr[DD*GG*HDIM];
__device__ float g_wvr[DD*GG*HDIM];
__device__ float g_wor[DD*DD];
__device__ int   g_counts[EE];
__device__ int   g_offs[EE+1];
__device__ int   g_te [NPAIR];
__device__ int   g_tr [NPAIR];
__device__ float g_tg [NPAIR];
__device__ int   g_pair[NPAIR];
__device__ int   g_slot[NPAIR];

// ---------------- helpers ----------------
__device__ __forceinline__ float tanh_approx(float x) {
    float y;
    asm("tanh.approx.f32 %0, %1;" : "=f"(y) : "f"(x));
    return y;
}
__device__ __forceinline__ float gelu_tanh(float x) {
    const float c0 = 0.7978845608028654f;
    float x3 = x * x * x;
    float t = tanh_approx(c0 * (x + 0.044715f * x3));
    return 0.5f * x * (1.0f + t);
}

template<class Frag>
__device__ __forceinline__ void frag_to_tf32(Frag& f) {
    #pragma unroll
    for (int i = 0; i < f.num_elements; i++)
        f.x[i] = wmma::__float_to_tf32(f.x[i]);
}

__device__ __forceinline__ void cp16(void* s, const void* g) {
    unsigned int sa = (unsigned int)__cvta_generic_to_shared(s);
    asm volatile("cp.async.cg.shared.global [%0], [%1], 16;\n" :: "r"(sa), "l"(g));
}
__device__ __forceinline__ void cp16z(void* s, const void* g, bool v) {
    unsigned int sa = (unsigned int)__cvta_generic_to_shared(s);
    int sz = v ? 16 : 0;
    asm volatile("cp.async.cg.shared.global [%0], [%1], 16, %2;\n" :: "r"(sa), "l"(g), "r"(sz));
}
__device__ __forceinline__ void cp_commit() { asm volatile("cp.async.commit_group;\n"); }
template<int N> __device__ __forceinline__ void cp_wait() {
    asm volatile("cp.async.wait_group %0;\n" :: "n"(N));
}

// ---------------- fp32 -> tf32(RN) rounding pass ----------------
__global__ void f2tf_kernel(const float* __restrict__ in,
                            float* __restrict__ out, int n4)
{
    int i = blockIdx.x * blockDim.x + threadIdx.x;
    if (i >= n4) return;
    float4 v = reinterpret_cast<const float4*>(in)[i];
    v.x = wmma::__float_to_tf32(v.x);
    v.y = wmma::__float_to_tf32(v.y);
    v.z = wmma::__float_to_tf32(v.z);
    v.w = wmma::__float_to_tf32(v.w);
    reinterpret_cast<float4*>(out)[i] = v;
}

// ---------------- LayerNorm. MODE: 0=exact, 1=rounded, 2=dual (exact + rounded copy) ----------------
template<int MODE>
__global__ void ln_kernel(const float* __restrict__ x,
                          const float* __restrict__ scale,
                          const float* __restrict__ bias,
                          float* __restrict__ out,
                          float* __restrict__ outr)
{
    __shared__ float red[8];
    int t = blockIdx.x, tid = threadIdx.x;
    const float4* xp = reinterpret_cast<const float4*>(x + (size_t)t * DD);
    float4 v = xp[tid];
    float s = v.x + v.y + v.z + v.w;
    #pragma unroll
    for (int o = 16; o; o >>= 1) s += __shfl_xor_sync(0xffffffffu, s, o);
    if ((tid & 31) == 0) red[tid >> 5] = s;
    __syncthreads();
    if (tid < 8) {
        float r = red[tid];
        #pragma unroll
        for (int o = 4; o; o >>= 1) r += __shfl_xor_sync(0xffu, r, o);
        if (tid == 0) red[0] = r;
    }
    __syncthreads();
    float mu = red[0] * (1.0f / DD);
    float d0 = v.x - mu, d1 = v.y - mu, d2 = v.z - mu, d3 = v.w - mu;
    float sq = d0*d0 + d1*d1 + d2*d2 + d3*d3;
    #pragma unroll
    for (int o = 16; o; o >>= 1) sq += __shfl_xor_sync(0xffffffffu, sq, o);
    __syncthreads();
    if ((tid & 31) == 0) red[tid >> 5] = sq;
    __syncthreads();
    if (tid < 8) {
        float r = red[tid];
        #pragma unroll
        for (int o = 4; o; o >>= 1) r += __shfl_xor_sync(0xffu, r, o);
        if (tid == 0) red[0] = r;
    }
    __syncthreads();
    float rstd = rsqrtf(red[0] * (1.0f / DD) + 1e-6f);
    float4 sc = reinterpret_cast<const float4*>(scale)[tid];
    float4 bi = reinterpret_cast<const float4*>(bias)[tid];
    float4 o4;
    o4.x = d0 * rstd * sc.x + bi.x;
    o4.y = d1 * rstd * sc.y + bi.y;
    o4.z = d2 * rstd * sc.z + bi.z;
    o4.w = d3 * rstd * sc.w + bi.w;
    if (MODE == 1) {
        o4.x = wmma::__float_to_tf32(o4.x);
        o4.y = wmma::__float_to_tf32(o4.y);
        o4.z = wmma::__float_to_tf32(o4.z);
        o4.w = wmma::__float_to_tf32(o4.w);
    }
    reinterpret_cast<float4*>(out + (size_t)t * DD)[tid] = o4;
    if (MODE == 2) {
        float4 r4;
        r4.x = wmma::__float_to_tf32(o4.x);
        r4.y = wmma::__float_to_tf32(o4.y);
        r4.z = wmma::__float_to_tf32(o4.z);
        r4.w = wmma::__float_to_tf32(o4.w);
        reinterpret_cast<float4*>(outr + (size_t)t * DD)[tid] = r4;
    }
}

// ---------------- tf32 GEMM, cp.async double-buffered, 128x128x32 (champion config) ----------------
// A operands MUST be pre-rounded to tf32 (RN). B: pre-rounded unless CVTB (in-frag RN).
#define BM 128
#define BN 128
#define BKT 32
#define ALD 40
#define BLD 136
#define GEMM_SMEM_FLOATS (2*128*ALD + 2*32*BLD + 8*256)

template<int ACT, bool RESID, bool GATHER, bool SEG, bool QKV, bool ROUT, bool CVTB>
__global__ __launch_bounds__(256, 2)
void gemm_tc(const float* __restrict__ A,
             const float* __restrict__ Bmat,
             const float* __restrict__ biasp,
             const float* __restrict__ resid,
             float* __restrict__ C,
             int M, int N, int Kd,
             const int* __restrict__ gather,
             const int* __restrict__ counts,
             const int* __restrict__ offs,
             size_t strideB, size_t strideBias,
             const float* __restrict__ B2, const float* __restrict__ bias2, float* __restrict__ C2,
             const float* __restrict__ B3, const float* __restrict__ bias3, float* __restrict__ C3)
{
    extern __shared__ float smem[];
    float* As    = smem;                       // [2][128][ALD]
    float* Bs    = As + 2 * 128 * ALD;         // [2][32][BLD]
    float* stage = Bs + 2 * 32 * BLD;          // [8][256]

    int off = 0, Mseg = M, Nn = N, bn;
    const float* Bm = Bmat;
    const float* bias = biasp;
    float* Cout = C;
    if (QKV) {
        int xb = blockIdx.x;
        if (xb < 8)       { bn = xb * 128; }
        else if (xb < 10) { Bm = B2; bias = bias2; Cout = C2; Nn = 256; bn = (xb - 8) * 128; }
        else              { Bm = B3; bias = bias3; Cout = C3; Nn = 256; bn = (xb - 10) * 128; }
    } else {
        bn = blockIdx.x * BN;
    }
    if (SEG) {
        int e = blockIdx.z;
        Mseg = counts[e];
        off  = offs[e];
        Bm   = Bmat + (size_t)e * strideB;
        bias = biasp + (size_t)e * strideBias;
    }
    int bm = blockIdx.y * BM;
    if (bm >= Mseg) return;

    int tid  = threadIdx.x;
    int wid  = tid >> 5;
    int lane = tid & 31;
    int wm   = wid & 3;
    int wn   = wid >> 2;

    int arow = tid >> 3;            // 0..31
    int acol = (tid & 7) * 4;       // 0..28
    const float* aptr[4];
    bool aok[4];
    #pragma unroll
    for (int p = 0; p < 4; p++) {
        int grow = bm + arow + p * 32;
        aok[p] = grow < Mseg;
        long src = 0;
        if (aok[p]) src = GATHER ? (long)gather[off + grow] : (long)(off + grow);
        aptr[p] = A + (size_t)src * Kd + acol;
    }
    int brow = tid >> 3;
    int bcol = (tid & 7) * 4;
    const float* bptr = Bm + (size_t)brow * Nn + bn + bcol;

    wmma::fragment<wmma::accumulator, 16, 16, 8, float> acc[2][4];
    #pragma unroll
    for (int i = 0; i < 2; i++)
        #pragma unroll
        for (int j = 0; j < 4; j++) wmma::fill_fragment(acc[i][j], 0.0f);

    int nk = Kd / BKT;

    {
        #pragma unroll
        for (int p = 0; p < 4; p++)
            cp16z(&As[(0 * 128 + arow + p * 32) * ALD + acol], aptr[p], aok[p]);
        #pragma unroll
        for (int p = 0; p < 4; p++)
            cp16(&Bs[(0 * 32 + brow) * BLD + bcol + p * 32], bptr + p * 32);
        cp_commit();
    }

    for (int it = 0; it < nk; it++) {
        int buf = it & 1;
        if (it + 1 < nk) {
            int k0 = (it + 1) * BKT;
            int nb = buf ^ 1;
            #pragma unroll
            for (int p = 0; p < 4; p++)
                cp16z(&As[(nb * 128 + arow + p * 32) * ALD + acol], aptr[p] + k0, aok[p]);
            #pragma unroll
            for (int p = 0; p < 4; p++)
                cp16(&Bs[(nb * 32 + brow) * BLD + bcol + p * 32],
                     bptr + (size_t)k0 * Nn + p * 32);
        }
        cp_commit();
        cp_wait<1>();
        __syncthreads();

        #pragma unroll
        for (int kk = 0; kk < BKT / 8; kk++) {
            wmma::fragment<wmma::matrix_a, 16, 16, 8, wmma::precision::tf32, wmma::row_major> af[2];
            wmma::fragment<wmma::matrix_b, 16, 16, 8, wmma::precision::tf32, wmma::row_major> bf[4];
            #pragma unroll
            for (int i = 0; i < 2; i++)
                wmma::load_matrix_sync(af[i], &As[(buf * 128 + wm * 32 + i * 16) * ALD + kk * 8], ALD);
            #pragma unroll
            for (int j = 0; j < 4; j++) {
                wmma::load_matrix_sync(bf[j], &Bs[(buf * 32 + kk * 8) * BLD + wn * 64 + j * 16], BLD);
                if (CVTB) frag_to_tf32(bf[j]);
            }
            #pragma unroll
            for (int i = 0; i < 2; i++)
                #pragma unroll
                for (int j = 0; j < 4; j++)
                    wmma::mma_sync(acc[i][j], af[i], bf[j], acc[i][j]);
        }
        __syncthreads();
    }

    int er  = lane >> 1;
    int ec0 = (lane & 1) * 8;
    #pragma unroll
    for (int i = 0; i < 2; i++) {
        #pragma unroll
        for (int j = 0; j < 4; j++) {
            wmma::store_matrix_sync(&stage[wid * 256], acc[i][j], 16, wmma::mem_row_major);
            __syncwarp();
            int grow = bm + wm * 32 + i * 16 + er;
            if (grow < Mseg) {
                int gcol = bn + wn * 64 + j * 16 + ec0;
                size_t cidx = (size_t)(off + grow) * Nn + gcol;
                float v[8];
                #pragma unroll
                for (int q = 0; q < 4; q++) {
                    v[q]     = stage[wid * 256 + er * 16 + ec0 + q]     + bias[gcol + q];
                    v[q + 4] = stage[wid * 256 + er * 16 + ec0 + 4 + q] + bias[gcol + 4 + q];
                }
                if (ACT == 1) {
                    #pragma unroll
                    for (int q = 0; q < 8; q++) v[q] = gelu_tanh(v[q]);
                }
                if (RESID) {
                    float4 r0 = *reinterpret_cast<const float4*>(&resid[cidx]);
                    float4 r1 = *reinterpret_cast<const float4*>(&resid[cidx + 4]);
                    v[0] += r0.x; v[1] += r0.y; v[2] += r0.z; v[3] += r0.w;
                    v[4] += r1.x; v[5] += r1.y; v[6] += r1.z; v[7] += r1.w;
                }
                if (ROUT) {
                    #pragma unroll
                    for (int q = 0; q < 8; q++) v[q] = wmma::__float_to_tf32(v[q]);
                }
                *reinterpret_cast<float4*>(&Cout[cidx])     = make_float4(v[0], v[1], v[2], v[3]);
                *reinterpret_cast<float4*>(&Cout[cidx + 4]) = make_float4(v[4], v[5], v[6], v[7]);
            }
            __syncwarp();
        }
    }
}

// ---------------- attention: tf32 wmma flash, 64q x 64k, K/V prefetch overlap ----------------
// P rounded to tf32 at softmax store (l_run sums unrounded) -> no frag CVT in PV.
#define APD 68
#define ATTN_SMEM_FLOATS (6*64*APD + 3*64)

__global__ __launch_bounds__(256, 2)
void attn_tc(const float* __restrict__ qb,
             const float* __restrict__ kb,
             const float* __restrict__ vb,
             const float* __restrict__ deltas,
             const float* __restrict__ time_decay,
             float* __restrict__ ob)
{
    extern __shared__ float sm[];
    float* qs  = sm;
    float* ks  = qs  + 64 * APD;
    float* vs  = ks  + 64 * APD;          // 2 buffers
    float* ps  = vs  + 2 * 64 * APD;
    float* os  = ps  + 64 * APD;
    float* dq_s = os + 64 * APD;
    float* dk_s = dq_s + 64;
    float* l_s  = dk_s + 64;

    int qt = blockIdx.x, h = blockIdx.y, b = blockIdx.z;
    int g = h >> 2;
    int tid = threadIdx.x;
    int wid = tid >> 5;
    float td = time_decay[h];
    float lam = (td > 20.f) ? td : log1pf(__expf(td));
    int q0 = qt * 64;

    {
        #pragma unroll
        for (int p = 0; p < 4; p++) {
            int ch = tid + p * 256;
            int r = ch >> 4, cc = (ch & 15) * 4;
            cp16(&qs[r * APD + cc],
                 qb + ((size_t)(b * SS + q0 + r)) * DD + h * HDIM + cc);
            size_t base = ((size_t)(b * SS + r)) * (GG * HDIM) + g * HDIM + cc;
            cp16(&ks[r * APD + cc], kb + base);
            cp16(&vs[r * APD + cc], vb + base);
        }
        cp_commit();
    }
    if (tid < 64) dq_s[tid] = deltas[b * SS + q0 + tid];
    #pragma unroll
    for (int p = 0; p < 16; p++) {
        int idx = tid + p * 256;
        os[(idx >> 6) * APD + (idx & 63)] = 0.f;
    }

    const float scale = 0.125f;
    int rw = wid & 3;
    int cw = wid >> 2;
    int prow = tid >> 2, psub = tid & 3;
    float m_prev = -INFINITY, l_run = 0.f;
    const int NT = SS / 64;

    for (int kt = 0; kt < NT; kt++) {
        int vbuf = kt & 1;
        if (tid < 64) dk_s[tid] = deltas[b * SS + kt * 64 + tid];
        cp_wait<0>();
        __syncthreads();

        // S = Q @ K^T
        {
            wmma::fragment<wmma::accumulator, 16, 16, 8, float> sacc[2];
            wmma::fill_fragment(sacc[0], 0.f);
            wmma::fill_fragment(sacc[1], 0.f);
            #pragma unroll
            for (int kk = 0; kk < 8; kk++) {
                wmma::fragment<wmma::matrix_a, 16, 16, 8, wmma::precision::tf32, wmma::row_major> af;
                wmma::fragment<wmma::matrix_b, 16, 16, 8, wmma::precision::tf32, wmma::col_major> bf[2];
                wmma::load_matrix_sync(af, &qs[(rw * 16) * APD + kk * 8], APD);
                #pragma unroll
                for (int j = 0; j < 2; j++)
                    wmma::load_matrix_sync(bf[j], &ks[(cw * 32 + j * 16) * APD + kk * 8], APD);
                #pragma unroll
                for (int j = 0; j < 2; j++)
                    wmma::mma_sync(sacc[j], af, bf[j], sacc[j]);
            }
            #pragma unroll
            for (int j = 0; j < 2; j++)
                wmma::store_matrix_sync(&ps[(rw * 16) * APD + cw * 32 + j * 16],
                                        sacc[j], APD, wmma::mem_row_major);
        }
        __syncthreads();

        // prefetch K/V[kt+1] (overlaps softmax + PV)
        if (kt + 1 < NT) {
            #pragma unroll
            for (int p = 0; p < 4; p++) {
                int ch = tid + p * 256;
                int r = ch >> 4, cc = (ch & 15) * 4;
                size_t base = ((size_t)(b * SS + (kt + 1) * 64 + r)) * (GG * HDIM) + g * HDIM + cc;
                cp16(&ks[r * APD + cc], kb + base);
                cp16(&vs[(vbuf ^ 1) * 64 * APD + r * APD + cc], vb + base);
            }
        }
        cp_commit();

        // softmax + alpha-scale of os rows; store tf32-rounded P
        {
            float dqv = dq_s[prow];
            float sv[16];
            float mt = -INFINITY;
            #pragma unroll
            for (int j = 0; j < 16; j++) {
                int c = psub * 16 + j;
                float s = ps[prow * APD + c] * scale - lam * fabsf(dqv - dk_s[c]);
                sv[j] = s;
                mt = fmaxf(mt, s);
            }
            mt = fmaxf(mt, __shfl_xor_sync(0xffffffffu, mt, 1));
            mt = fmaxf(mt, __shfl_xor_sync(0xffffffffu, mt, 2));
            float m_new = fmaxf(m_prev, mt);
            float alpha = __expf(m_prev - m_new);
            float sum = 0.f;
            #pragma unroll
            for (int j = 0; j < 16; j++) {
                float p = __expf(sv[j] - m_new);
                ps[prow * APD + psub * 16 + j] = wmma::__float_to_tf32(p);
                sum += p;     // l_run uses unrounded p (same as before)
            }
            sum += __shfl_xor_sync(0xffffffffu, sum, 1);
            sum += __shfl_xor_sync(0xffffffffu, sum, 2);
            l_run = l_run * alpha + sum;
            m_prev = m_new;
            #pragma unroll
            for (int j = 0; j < 16; j++)
                os[prow * APD + psub * 16 + j] *= alpha;
        }
        __syncthreads();

        // os += P @ V[vbuf]  (P already tf32-rounded in smem)
        {
            wmma::fragment<wmma::accumulator, 16, 16, 8, float> pacc[2];
            #pragma unroll
            for (int j = 0; j < 2; j++)
                wmma::load_matrix_sync(pacc[j], &os[(rw * 16) * APD + cw * 32 + j * 16],
                                       APD, wmma::mem_row_major);
            #pragma unroll
            for (int kk = 0; kk < 8; kk++) {
                wmma::fragment<wmma::matrix_a, 16, 16, 8, wmma::precision::tf32, wmma::row_major> af;
                wmma::fragment<wmma::matrix_b, 16, 16, 8, wmma::precision::tf32, wmma::row_major> bf[2];
                wmma::load_matrix_sync(af, &ps[(rw * 16) * APD + kk * 8], APD);
                #pragma unroll
                for (int j = 0; j < 2; j++)
                    wmma::load_matrix_sync(bf[j], &vs[vbuf * 64 * APD + (kk * 8) * APD + cw * 32 + j * 16], APD);
                #pragma unroll
                for (int j = 0; j < 2; j++)
                    wmma::mma_sync(pacc[j], af, bf[j], pacc[j]);
            }
            #pragma unroll
            for (int j = 0; j < 2; j++)
                wmma::store_matrix_sync(&os[(rw * 16) * APD + cw * 32 + j * 16],
                                        pacc[j], APD, wmma::mem_row_major);
        }
    }
    __syncthreads();
    if (psub == 0) l_s[prow] = l_run;
    __syncthreads();
    #pragma unroll
    for (int p = 0; p < 16; p++) {
        int idx = tid + p * 256;
        int r = idx >> 6, c = idx & 63;
        ob[((size_t)(b * SS + q0 + r)) * DD + h * HDIM + c] =
            wmma::__float_to_tf32(os[r * APD + c] / l_s[r]);
    }
}

// ---------------- router + bucketing ----------------
__global__ void zero_kernel(int* counts) {
    if (threadIdx.x < EE) counts[threadIdx.x] = 0;
}

__global__ void router_kernel(const float* __restrict__ xn2,
                              const float* __restrict__ rw,
                              const float* __restrict__ rb,
                              int* __restrict__ counts,
                              int* __restrict__ te,
                              int* __restrict__ tr,
                              float* __restrict__ tg)
{
    __shared__ float lg[EE];
    int t = blockIdx.x, tid = threadIdx.x;
    int w = tid >> 5, lane = tid & 31;
    const float* xr = xn2 + (size_t)t * DD;
    float p = 0.f;
    for (int d = lane; d < DD; d += 32)
        p += xr[d] * rw[d * EE + w];
    #pragma unroll
    for (int o = 16; o; o >>= 1) p += __shfl_xor_sync(0xffffffffu, p, o);
    if (lane == 0) lg[w] = p + rb[w];
    __syncthreads();
    if (tid == 0) {
        float best = -INFINITY, second = -INFINITY;
        int i0 = 0, i1 = 0;
        #pragma unroll
        for (int e = 0; e < EE; e++) {
            float v = lg[e];
            if (v > best)        { second = best; i1 = i0; best = v; i0 = e; }
            else if (v > second) { second = v; i1 = e; }
        }
        float g0 = 1.0f / (1.0f + expf(second - best));
        float g1 = 1.0f - g0;
        int r0 = atomicAdd(&counts[i0], 1);
        int r1 = atomicAdd(&counts[i1], 1);
        te[t * 2 + 0] = i0; te[t * 2 + 1] = i1;
        tr[t * 2 + 0] = r0; tr[t * 2 + 1] = r1;
        tg[t * 2 + 0] = g0; tg[t * 2 + 1] = g1;
    }
}

__global__ void offs_kernel(const int* __restrict__ counts, int* __restrict__ offs) {
    if (threadIdx.x == 0 && blockIdx.x == 0) {
        int acc = 0;
        for (int e = 0; e < EE; e++) { offs[e] = acc; acc += counts[e]; }
        offs[EE] = acc;
    }
}

__global__ void pack_kernel(const int* __restrict__ te, const int* __restrict__ tr,
                            const int* __restrict__ offs,
                            int* __restrict__ pair, int* __restrict__ slot)
{
    int t = blockIdx.x * blockDim.x + threadIdx.x;
    if (t >= TT) return;
    #pragma unroll
    for (int k2 = 0; k2 < 2; k2++) {
        int e = te[t * 2 + k2];
        int s = offs[e] + tr[t * 2 + k2];
        pair[s] = t;
        slot[t * 2 + k2] = s;
    }
}

__global__ void combine_kernel(const int* __restrict__ slot,
                               const float* __restrict__ tg,
                               const float* __restrict__ ybuf,
                               float* __restrict__ out)
{
    int t = blockIdx.x, tid = threadIdx.x;
    int s0 = slot[t * 2], s1 = slot[t * 2 + 1];
    float g0 = tg[t * 2], g1 = tg[t * 2 + 1];
    const float4* y0 = reinterpret_cast<const float4*>(ybuf + (size_t)s0 * DD);
    const float4* y1 = reinterpret_cast<const float4*>(ybuf + (size_t)s1 * DD);
    float4* op = reinterpret_cast<float4*>(out + (size_t)t * DD);
    float4 a = op[tid], b0 = y0[tid], b1 = y1[tid];
    a.x += g0 * b0.x + g1 * b1.x;
    a.y += g0 * b0.y + g1 * b1.y;
    a.z += g0 * b0.z + g1 * b1.z;
    a.w += g0 * b0.w + g1 * b1.w;
    op[tid] = a;
}

// ---------------- launch ----------------
extern "C" void kernel_launch(void* const* d_in, const int* in_sizes, int n_in,
                              void* d_out, int out_size)
{
    const float* x      = (const float*)d_in[0];
    const float* deltas = (const float*)d_in[1];
    const float* ln1_s  = (const float*)d_in[2];
    const float* ln1_b  = (const float*)d_in[3];
    const float* wq     = (const float*)d_in[4];
    const float* bq     = (const float*)d_in[5];
    const float* wk     = (const float*)d_in[6];
    const float* bk     = (const float*)d_in[7];
    const float* wv     = (const float*)d_in[8];
    const float* bv     = (const float*)d_in[9];
    const float* wo     = (const float*)d_in[10];
    const float* bo     = (const float*)d_in[11];
    const float* tdcy   = (const float*)d_in[12];
    const float* ln2_s  = (const float*)d_in[13];
    const float* ln2_b  = (const float*)d_in[14];
    const float* rw     = (const float*)d_in[15];
    const float* rb     = (const float*)d_in[16];
    const float* w1     = (const float*)d_in[17];
    const float* b1     = (const float*)d_in[18];
    const float* w2     = (const float*)d_in[19];
    const float* b2     = (const float*)d_in[20];
    float* out = (float*)d_out;

    float *p_xn, *p_q, *p_k, *p_v, *p_o, *p_xn2, *p_xn2r, *p_h, *p_y, *p_tg;
    float *p_wqr, *p_wkr, *p_wvr, *p_wor;
    int *p_counts, *p_offs, *p_te, *p_tr, *p_pair, *p_slot;
    cudaGetSymbolAddress((void**)&p_xn,  g_xn);
    cudaGetSymbolAddress((void**)&p_q,   g_q);
    cudaGetSymbolAddress((void**)&p_k,   g_k);
    cudaGetSymbolAddress((void**)&p_v,   g_v);
    cudaGetSymbolAddress((void**)&p_o,   g_o);
    cudaGetSymbolAddress((void**)&p_xn2, g_xn2);
    cudaGetSymbolAddress((void**)&p_xn2r, g_xn2r);
    cudaGetSymbolAddress((void**)&p_h,   g_h);
    cudaGetSymbolAddress((void**)&p_y,   g_y);
    cudaGetSymbolAddress((void**)&p_wqr, g_wqr);
    cudaGetSymbolAddress((void**)&p_wkr, g_wkr);
    cudaGetSymbolAddress((void**)&p_wvr, g_wvr);
    cudaGetSymbolAddress((void**)&p_wor, g_wor);
    cudaGetSymbolAddress((void**)&p_counts, g_counts);
    cudaGetSymbolAddress((void**)&p_offs,   g_offs);
    cudaGetSymbolAddress((void**)&p_te,     g_te);
    cudaGetSymbolAddress((void**)&p_tr,     g_tr);
    cudaGetSymbolAddress((void**)&p_tg,     g_tg);
    cudaGetSymbolAddress((void**)&p_pair,   g_pair);
    cudaGetSymbolAddress((void**)&p_slot,   g_slot);

    const int GEMM_SMEM = GEMM_SMEM_FLOATS * (int)sizeof(float);
    const int ATTN_SMEM = ATTN_SMEM_FLOATS * (int)sizeof(float);
    static bool attr_done = false;
    if (!attr_done) {
        cudaFuncSetAttribute(gemm_tc<0, false, false, false, true,  true,  false>,
                             cudaFuncAttributeMaxDynamicSharedMemorySize, GEMM_SMEM);
        cudaFuncSetAttribute(gemm_tc<0, true,  false, false, false, false, false>,
                             cudaFuncAttributeMaxDynamicSharedMemorySize, GEMM_SMEM);
        cudaFuncSetAttribute(gemm_tc<1, false, true,  true,  false, true,  true >,
                             cudaFuncAttributeMaxDynamicSharedMemorySize, GEMM_SMEM);
        cudaFuncSetAttribute(gemm_tc<0, false, false, true,  false, false, true >,
                             cudaFuncAttributeMaxDynamicSharedMemorySize, GEMM_SMEM);
        cudaFuncSetAttribute(attn_tc,
                             cudaFuncAttributeMaxDynamicSharedMemorySize, ATTN_SMEM);
        attr_done = true;
    }

    // 0) LN1 (rounded output: feeds QKV GEMM only)
    ln_kernel<1><<<TT, 256>>>(x, ln1_s, ln1_b, p_xn, nullptr);
    // 1-4) pre-round small weights (cheap; avoids in-loop CVT in QKV/O-proj)
    f2tf_kernel<<<(DD * DD / 4 + 255) / 256, 256>>>(wq, p_wqr, DD * DD / 4);
    f2tf_kernel<<<(DD * GG * HDIM / 4 + 255) / 256, 256>>>(wk, p_wkr, DD * GG * HDIM / 4);
    f2tf_kernel<<<(DD * GG * HDIM / 4 + 255) / 256, 256>>>(wv, p_wvr, DD * GG * HDIM / 4);
    f2tf_kernel<<<(DD * DD / 4 + 255) / 256, 256>>>(wo, p_wor, DD * DD / 4);
    // 5) fused Q/K/V projection (pre-rounded weights; outputs rounded)
    gemm_tc<0, false, false, false, true, true, false><<<dim3(12, TT / BM, 1), 256, GEMM_SMEM>>>(
        p_xn, p_wqr, bq, nullptr, p_q, TT, DD, DD, nullptr, nullptr, nullptr, 0, 0,
        p_wkr, bk, p_k, p_wvr, bv, p_v);
    // 6) attention (output rounded for O-proj)
    attn_tc<<<dim3(SS / 64, HH, BB), 256, ATTN_SMEM>>>(p_q, p_k, p_v, deltas, tdcy, p_o);
    // 7) output projection + residual (pre-rounded wo; exact out)
    gemm_tc<0, true, false, false, false, false, false><<<dim3(DD / BN, TT / BM, 1), 256, GEMM_SMEM>>>(
        p_o, p_wor, bo, x, out, TT, DD, DD, nullptr, nullptr, nullptr, 0, 0,
        nullptr, nullptr, nullptr, nullptr, nullptr, nullptr);
    // 8) LN2 dual: exact (router) + rounded (GEMM1 A)
    ln_kernel<2><<<TT, 256>>>(out, ln2_s, ln2_b, p_xn2, p_xn2r);
    // 9) router + bucketing
    zero_kernel<<<1, 32>>>(p_counts);
    router_kernel<<<TT, 256>>>(p_xn2, rw, rb, p_counts, p_te, p_tr, p_tg);
    offs_kernel<<<1, 1>>>(p_counts, p_offs);
    pack_kernel<<<TT / 256, 256>>>(p_te, p_tr, p_offs, p_pair, p_slot);
    // 10) expert GEMM1 (gathered, HW-tanh gelu, rounded h out; w1 raw, in-frag CVT)
    gemm_tc<1, false, true, true, false, true, true><<<dim3(FF / BN, NPAIR / BM, EE), 256, GEMM_SMEM>>>(
        p_xn2r, w1, b1, nullptr, p_h, 0, FF, DD, p_pair, p_counts, p_offs,
        (size_t)DD * FF, (size_t)FF,
        nullptr, nullptr, nullptr, nullptr, nullptr, nullptr);
    // 11) expert GEMM2 (exact y out; w2 raw, in-frag CVT)
    gemm_tc<0, false, false, true, false, false, true><<<dim3(DD / BN, NPAIR / BM, EE), 256, GEMM_SMEM>>>(
        p_h, w2, b2, nullptr, p_y, 0, DD, FF, nullptr, p_counts, p_offs,
        (size_t)FF * DD, (size_t)DD,
        nullptr, nullptr, nullptr, nullptr, nullptr, nullptr);
    // 12) combine
    combine_kernel<<<TT, 256>>>(p_slot, p_tg, p_y, out);

    (void)in_sizes; (void)n_in; (void)out_size;
}

// round 16
// speedup vs baseline: 1.2473x; 1.2437x over previous
#include <cuda_runtime.h>
#include <cuda_bf16.h>
#include <cstdint>
#include <math.h>
#include <mma.h>

using namespace nvcuda;

// ---------------- problem constants ----------------
#define BB   2
#define SS   2048
#define TT   4096          // B*S tokens
#define DD   1024
#define HH   16
#define GG   4
#define HDIM 64
#define EE   8
#define FF   4096
#define NPAIR (TT*2)

// ---------------- scratch ----------------
__device__ float g_xn [TT*DD];           // tf32-rounded
__device__ float g_q  [TT*DD];           // tf32-rounded
__device__ float g_k  [TT*GG*HDIM];      // tf32-rounded
__device__ float g_v  [TT*GG*HDIM];      // tf32-rounded
__device__ float g_o  [TT*DD];           // tf32-rounded
__device__ float g_xn2 [TT*DD];          // exact (router)
__device__ float g_xn2r[TT*DD];          // tf32-rounded (GEMM1 A)
__device__ __nv_bfloat16 g_hb [(size_t)NPAIR*FF];  // 67 MB gelu out (bf16)
__device__ __nv_bfloat16 g_w2b[(size_t)EE*FF*DD];  // 67 MB w2 (bf16)
__device__ float g_y  [(size_t)NPAIR*DD];   // exact
__device__ float g_wqr[DD*DD];
__device__ float g_wkr[DD*GG*HDIM];
__device__ float g_wvr[DD*GG*HDIM];
__device__ float g_wor[DD*DD];
__device__ int   g_counts[EE];
__device__ int   g_offs[EE+1];
__device__ int   g_te [NPAIR];
__device__ int   g_tr [NPAIR];
__device__ float g_tg [NPAIR];
__device__ int   g_pair[NPAIR];
__device__ int   g_slot[NPAIR];

// ---------------- helpers ----------------
__device__ __forceinline__ float tanh_approx(float x) {
    float y;
    asm("tanh.approx.f32 %0, %1;" : "=f"(y) : "f"(x));
    return y;
}
__device__ __forceinline__ float gelu_tanh(float x) {
    const float c0 = 0.7978845608028654f;
    float x3 = x * x * x;
    float t = tanh_approx(c0 * (x + 0.044715f * x3));
    return 0.5f * x * (1.0f + t);
}

template<class Frag>
__device__ __forceinline__ void frag_to_tf32(Frag& f) {
    #pragma unroll
    for (int i = 0; i < f.num_elements; i++)
        f.x[i] = wmma::__float_to_tf32(f.x[i]);
}

__device__ __forceinline__ void cp16(void* s, const void* g) {
    unsigned int sa = (unsigned int)__cvta_generic_to_shared(s);
    asm volatile("cp.async.cg.shared.global [%0], [%1], 16;\n" :: "r"(sa), "l"(g));
}
__device__ __forceinline__ void cp16z(void* s, const void* g, bool v) {
    unsigned int sa = (unsigned int)__cvta_generic_to_shared(s);
    int sz = v ? 16 : 0;
    asm volatile("cp.async.cg.shared.global [%0], [%1], 16, %2;\n" :: "r"(sa), "l"(g), "r"(sz));
}
__device__ __forceinline__ void cp_commit() { asm volatile("cp.async.commit_group;\n"); }
template<int N> __device__ __forceinline__ void cp_wait() {
    asm volatile("cp.async.wait_group %0;\n" :: "n"(N));
}

// ---------------- fp32 -> tf32(RN) rounding pass ----------------
__global__ void f2tf_kernel(const float* __restrict__ in,
                            float* __restrict__ out, int n4)
{
    int i = blockIdx.x * blockDim.x + threadIdx.x;
    if (i >= n4) return;
    float4 v = reinterpret_cast<const float4*>(in)[i];
    v.x = wmma::__float_to_tf32(v.x);
    v.y = wmma::__float_to_tf32(v.y);
    v.z = wmma::__float_to_tf32(v.z);
    v.w = wmma::__float_to_tf32(v.w);
    reinterpret_cast<float4*>(out)[i] = v;
}

// ---------------- fp32 -> bf16 conversion ----------------
__global__ void f2bf_kernel(const float* __restrict__ in,
                            __nv_bfloat16* __restrict__ out, int n4)
{
    int i = blockIdx.x * blockDim.x + threadIdx.x;
    if (i >= n4) return;
    float4 v = reinterpret_cast<const float4*>(in)[i];
    __nv_bfloat162 a = __floats2bfloat162_rn(v.x, v.y);
    __nv_bfloat162 b = __floats2bfloat162_rn(v.z, v.w);
    uint2 u;
    u.x = *reinterpret_cast<unsigned int*>(&a);
    u.y = *reinterpret_cast<unsigned int*>(&b);
    reinterpret_cast<uint2*>(out)[i] = u;
}

// ---------------- LayerNorm. MODE: 0=exact, 1=rounded, 2=dual ----------------
template<int MODE>
__global__ void ln_kernel(const float* __restrict__ x,
                          const float* __restrict__ scale,
                          const float* __restrict__ bias,
                          float* __restrict__ out,
                          float* __restrict__ outr)
{
    __shared__ float red[8];
    int t = blockIdx.x, tid = threadIdx.x;
    const float4* xp = reinterpret_cast<const float4*>(x + (size_t)t * DD);
    float4 v = xp[tid];
    float s = v.x + v.y + v.z + v.w;
    #pragma unroll
    for (int o = 16; o; o >>= 1) s += __shfl_xor_sync(0xffffffffu, s, o);
    if ((tid & 31) == 0) red[tid >> 5] = s;
    __syncthreads();
    if (tid < 8) {
        float r = red[tid];
        #pragma unroll
        for (int o = 4; o; o >>= 1) r += __shfl_xor_sync(0xffu, r, o);
        if (tid == 0) red[0] = r;
    }
    __syncthreads();
    float mu = red[0] * (1.0f / DD);
    float d0 = v.x - mu, d1 = v.y - mu, d2 = v.z - mu, d3 = v.w - mu;
    float sq = d0*d0 + d1*d1 + d2*d2 + d3*d3;
    #pragma unroll
    for (int o = 16; o; o >>= 1) sq += __shfl_xor_sync(0xffffffffu, sq, o);
    __syncthreads();
    if ((tid & 31) == 0) red[tid >> 5] = sq;
    __syncthreads();
    if (tid < 8) {
        float r = red[tid];
        #pragma unroll
        for (int o = 4; o; o >>= 1) r += __shfl_xor_sync(0xffu, r, o);
        if (tid == 0) red[0] = r;
    }
    __syncthreads();
    float rstd = rsqrtf(red[0] * (1.0f / DD) + 1e-6f);
    float4 sc = reinterpret_cast<const float4*>(scale)[tid];
    float4 bi = reinterpret_cast<const float4*>(bias)[tid];
    float4 o4;
    o4.x = d0 * rstd * sc.x + bi.x;
    o4.y = d1 * rstd * sc.y + bi.y;
    o4.z = d2 * rstd * sc.z + bi.z;
    o4.w = d3 * rstd * sc.w + bi.w;
    if (MODE == 1) {
        o4.x = wmma::__float_to_tf32(o4.x);
        o4.y = wmma::__float_to_tf32(o4.y);
        o4.z = wmma::__float_to_tf32(o4.z);
        o4.w = wmma::__float_to_tf32(o4.w);
    }
    reinterpret_cast<float4*>(out + (size_t)t * DD)[tid] = o4;
    if (MODE == 2) {
        float4 r4;
        r4.x = wmma::__float_to_tf32(o4.x);
        r4.y = wmma::__float_to_tf32(o4.y);
        r4.z = wmma::__float_to_tf32(o4.z);
        r4.w = wmma::__float_to_tf32(o4.w);
        reinterpret_cast<float4*>(outr + (size_t)t * DD)[tid] = r4;
    }
}

// ---------------- tf32 GEMM, cp.async double-buffered, 128x128x32 (champion) ----------------
#define BM 128
#define BN 128
#define BKT 32
#define ALD 40
#define BLD 136
#define GEMM_SMEM_FLOATS (2*128*ALD + 2*32*BLD + 8*256)

template<int ACT, bool RESID, bool GATHER, bool SEG, bool QKV, bool ROUT, bool CVTB, bool B16O>
__global__ __launch_bounds__(256, 2)
void gemm_tc(const float* __restrict__ A,
             const float* __restrict__ Bmat,
             const float* __restrict__ biasp,
             const float* __restrict__ resid,
             float* __restrict__ C,
             int M, int N, int Kd,
             const int* __restrict__ gather,
             const int* __restrict__ counts,
             const int* __restrict__ offs,
             size_t strideB, size_t strideBias,
             const float* __restrict__ B2, const float* __restrict__ bias2, float* __restrict__ C2,
             const float* __restrict__ B3, const float* __restrict__ bias3, float* __restrict__ C3)
{
    extern __shared__ float smem[];
    float* As    = smem;
    float* Bs    = As + 2 * 128 * ALD;
    float* stage = Bs + 2 * 32 * BLD;

    int off = 0, Mseg = M, Nn = N, bn;
    const float* Bm = Bmat;
    const float* bias = biasp;
    float* Cout = C;
    if (QKV) {
        int xb = blockIdx.x;
        if (xb < 8)       { bn = xb * 128; }
        else if (xb < 10) { Bm = B2; bias = bias2; Cout = C2; Nn = 256; bn = (xb - 8) * 128; }
        else              { Bm = B3; bias = bias3; Cout = C3; Nn = 256; bn = (xb - 10) * 128; }
    } else {
        bn = blockIdx.x * BN;
    }
    if (SEG) {
        int e = blockIdx.z;
        Mseg = counts[e];
        off  = offs[e];
        Bm   = Bmat + (size_t)e * strideB;
        bias = biasp + (size_t)e * strideBias;
    }
    int bm = blockIdx.y * BM;
    if (bm >= Mseg) return;

    int tid  = threadIdx.x;
    int wid  = tid >> 5;
    int lane = tid & 31;
    int wm   = wid & 3;
    int wn   = wid >> 2;

    int arow = tid >> 3;
    int acol = (tid & 7) * 4;
    const float* aptr[4];
    bool aok[4];
    #pragma unroll
    for (int p = 0; p < 4; p++) {
        int grow = bm + arow + p * 32;
        aok[p] = grow < Mseg;
        long src = 0;
        if (aok[p]) src = GATHER ? (long)gather[off + grow] : (long)(off + grow);
        aptr[p] = A + (size_t)src * Kd + acol;
    }
    int brow = tid >> 3;
    int bcol = (tid & 7) * 4;
    const float* bptr = Bm + (size_t)brow * Nn + bn + bcol;

    wmma::fragment<wmma::accumulator, 16, 16, 8, float> acc[2][4];
    #pragma unroll
    for (int i = 0; i < 2; i++)
        #pragma unroll
        for (int j = 0; j < 4; j++) wmma::fill_fragment(acc[i][j], 0.0f);

    int nk = Kd / BKT;

    {
        #pragma unroll
        for (int p = 0; p < 4; p++)
            cp16z(&As[(0 * 128 + arow + p * 32) * ALD + acol], aptr[p], aok[p]);
        #pragma unroll
        for (int p = 0; p < 4; p++)
            cp16(&Bs[(0 * 32 + brow) * BLD + bcol + p * 32], bptr + p * 32);
        cp_commit();
    }

    for (int it = 0; it < nk; it++) {
        int buf = it & 1;
        if (it + 1 < nk) {
            int k0 = (it + 1) * BKT;
            int nb = buf ^ 1;
            #pragma unroll
            for (int p = 0; p < 4; p++)
                cp16z(&As[(nb * 128 + arow + p * 32) * ALD + acol], aptr[p] + k0, aok[p]);
            #pragma unroll
            for (int p = 0; p < 4; p++)
                cp16(&Bs[(nb * 32 + brow) * BLD + bcol + p * 32],
                     bptr + (size_t)k0 * Nn + p * 32);
        }
        cp_commit();
        cp_wait<1>();
        __syncthreads();

        #pragma unroll
        for (int kk = 0; kk < BKT / 8; kk++) {
            wmma::fragment<wmma::matrix_a, 16, 16, 8, wmma::precision::tf32, wmma::row_major> af[2];
            wmma::fragment<wmma::matrix_b, 16, 16, 8, wmma::precision::tf32, wmma::row_major> bf[4];
            #pragma unroll
            for (int i = 0; i < 2; i++)
                wmma::load_matrix_sync(af[i], &As[(buf * 128 + wm * 32 + i * 16) * ALD + kk * 8], ALD);
            #pragma unroll
            for (int j = 0; j < 4; j++) {
                wmma::load_matrix_sync(bf[j], &Bs[(buf * 32 + kk * 8) * BLD + wn * 64 + j * 16], BLD);
                if (CVTB) frag_to_tf32(bf[j]);
            }
            #pragma unroll
            for (int i = 0; i < 2; i++)
                #pragma unroll
                for (int j = 0; j < 4; j++)
                    wmma::mma_sync(acc[i][j], af[i], bf[j], acc[i][j]);
        }
        __syncthreads();
    }

    int er  = lane >> 1;
    int ec0 = (lane & 1) * 8;
    #pragma unroll
    for (int i = 0; i < 2; i++) {
        #pragma unroll
        for (int j = 0; j < 4; j++) {
            wmma::store_matrix_sync(&stage[wid * 256], acc[i][j], 16, wmma::mem_row_major);
            __syncwarp();
            int grow = bm + wm * 32 + i * 16 + er;
            if (grow < Mseg) {
                int gcol = bn + wn * 64 + j * 16 + ec0;
                size_t cidx = (size_t)(off + grow) * Nn + gcol;
                float v[8];
                #pragma unroll
                for (int q = 0; q < 4; q++) {
                    v[q]     = stage[wid * 256 + er * 16 + ec0 + q]     + bias[gcol + q];
                    v[q + 4] = stage[wid * 256 + er * 16 + ec0 + 4 + q] + bias[gcol + 4 + q];
                }
                if (ACT == 1) {
                    #pragma unroll
                    for (int q = 0; q < 8; q++) v[q] = gelu_tanh(v[q]);
                }
                if (RESID) {
                    float4 r0 = *reinterpret_cast<const float4*>(&resid[cidx]);
                    float4 r1 = *reinterpret_cast<const float4*>(&resid[cidx + 4]);
                    v[0] += r0.x; v[1] += r0.y; v[2] += r0.z; v[3] += r0.w;
                    v[4] += r1.x; v[5] += r1.y; v[6] += r1.z; v[7] += r1.w;
                }
                if (ROUT) {
                    #pragma unroll
                    for (int q = 0; q < 8; q++) v[q] = wmma::__float_to_tf32(v[q]);
                }
                if (B16O) {
                    __nv_bfloat16* Cb = reinterpret_cast<__nv_bfloat16*>(Cout);
                    __nv_bfloat162 h0 = __floats2bfloat162_rn(v[0], v[1]);
                    __nv_bfloat162 h1 = __floats2bfloat162_rn(v[2], v[3]);
                    __nv_bfloat162 h2 = __floats2bfloat162_rn(v[4], v[5]);
                    __nv_bfloat162 h3 = __floats2bfloat162_rn(v[6], v[7]);
                    uint4 u;
                    u.x = *reinterpret_cast<unsigned int*>(&h0);
                    u.y = *reinterpret_cast<unsigned int*>(&h1);
                    u.z = *reinterpret_cast<unsigned int*>(&h2);
                    u.w = *reinterpret_cast<unsigned int*>(&h3);
                    *reinterpret_cast<uint4*>(&Cb[cidx]) = u;
                } else {
                    *reinterpret_cast<float4*>(&Cout[cidx])     = make_float4(v[0], v[1], v[2], v[3]);
                    *reinterpret_cast<float4*>(&Cout[cidx + 4]) = make_float4(v[4], v[5], v[6], v[7]);
                }
            }
            __syncwarp();
        }
    }
}

// ---------------- bf16 GEMM (MoE GEMM2), cp.async double-buffered, 128x128x32 ----------------
#define HALD 40     // bf16 lead dim A
#define HBLD 136    // bf16 lead dim B
#define GEMM_BF_SMEM (2*128*HALD*2 + 2*32*HBLD*2 + 8*256*4)

__global__ __launch_bounds__(256, 2)
void gemm_bf(const __nv_bfloat16* __restrict__ A,
             const __nv_bfloat16* __restrict__ Bmat,
             const float* __restrict__ biasp,
             float* __restrict__ Cf,
             int N, int Kd,
             const int* __restrict__ counts,
             const int* __restrict__ offs,
             size_t strideB, size_t strideBias)
{
    extern __shared__ char smemc[];
    __nv_bfloat16* As = reinterpret_cast<__nv_bfloat16*>(smemc);
    __nv_bfloat16* Bs = As + 2 * 128 * HALD;
    float* stage = reinterpret_cast<float*>(Bs + 2 * 32 * HBLD);

    int e = blockIdx.z;
    int Mseg = counts[e];
    int off  = offs[e];
    const __nv_bfloat16* Bm = Bmat + (size_t)e * strideB;
    const float* bias = biasp + (size_t)e * strideBias;
    int bm = blockIdx.y * BM;
    if (bm >= Mseg) return;
    int bn = blockIdx.x * BN;

    int tid  = threadIdx.x;
    int wid  = tid >> 5;
    int lane = tid & 31;
    int wm   = wid & 3;
    int wn   = wid >> 2;

    int ar0 = tid >> 2;                // 0..63
    int ach = (tid & 3) * 8;
    const __nv_bfloat16* aptr[2];
    bool aok[2];
    #pragma unroll
    for (int p = 0; p < 2; p++) {
        int grow = bm + ar0 + p * 64;
        aok[p] = grow < Mseg;
        long src = aok[p] ? (long)(off + grow) : 0;
        aptr[p] = A + (size_t)src * Kd + ach;
    }
    int br0 = tid >> 4;                // 0..15
    int bch = (tid & 15) * 8;
    const __nv_bfloat16* bptr = Bm + (size_t)br0 * N + bn + bch;

    wmma::fragment<wmma::accumulator, 16, 16, 16, float> acc[2][4];
    #pragma unroll
    for (int i = 0; i < 2; i++)
        #pragma unroll
        for (int j = 0; j < 4; j++) wmma::fill_fragment(acc[i][j], 0.0f);

    int nk = Kd / BKT;

    {
        #pragma unroll
        for (int p = 0; p < 2; p++)
            cp16z(&As[(0 * 128 + ar0 + p * 64) * HALD + ach], aptr[p], aok[p]);
        #pragma unroll
        for (int p = 0; p < 2; p++)
            cp16(&Bs[(0 * 32 + br0 + p * 16) * HBLD + bch], bptr + (size_t)(p * 16) * N);
        cp_commit();
    }

    for (int it = 0; it < nk; it++) {
        int buf = it & 1;
        if (it + 1 < nk) {
            int k0 = (it + 1) * BKT;
            int nb = buf ^ 1;
            #pragma unroll
            for (int p = 0; p < 2; p++)
                cp16z(&As[(nb * 128 + ar0 + p * 64) * HALD + ach], aptr[p] + k0, aok[p]);
            #pragma unroll
            for (int p = 0; p < 2; p++)
                cp16(&Bs[(nb * 32 + br0 + p * 16) * HBLD + bch],
                     bptr + (size_t)(k0 + p * 16) * N);
        }
        cp_commit();
        cp_wait<1>();
        __syncthreads();

        #pragma unroll
        for (int kk = 0; kk < BKT / 16; kk++) {
            wmma::fragment<wmma::matrix_a, 16, 16, 16, __nv_bfloat16, wmma::row_major> af[2];
            wmma::fragment<wmma::matrix_b, 16, 16, 16, __nv_bfloat16, wmma::row_major> bf[4];
            #pragma unroll
            for (int i = 0; i < 2; i++)
                wmma::load_matrix_sync(af[i], &As[(buf * 128 + wm * 32 + i * 16) * HALD + kk * 16], HALD);
            #pragma unroll
            for (int j = 0; j < 4; j++)
                wmma::load_matrix_sync(bf[j], &Bs[(buf * 32 + kk * 16) * HBLD + wn * 64 + j * 16], HBLD);
            #pragma unroll
            for (int i = 0; i < 2; i++)
                #pragma unroll
                for (int j = 0; j < 4; j++)
                    wmma::mma_sync(acc[i][j], af[i], bf[j], acc[i][j]);
        }
        __syncthreads();
    }

    int er  = lane >> 1;
    int ec0 = (lane & 1) * 8;
    #pragma unroll
    for (int i = 0; i < 2; i++) {
        #pragma unroll
        for (int j = 0; j < 4; j++) {
            wmma::store_matrix_sync(&stage[wid * 256], acc[i][j], 16, wmma::mem_row_major);
            __syncwarp();
            int grow = bm + wm * 32 + i * 16 + er;
            if (grow < Mseg) {
                int gcol = bn + wn * 64 + j * 16 + ec0;
                size_t cidx = (size_t)(off + grow) * N + gcol;
                float v[8];
                #pragma unroll
                for (int q = 0; q < 8; q++)
                    v[q] = stage[wid * 256 + er * 16 + ec0 + q] + bias[gcol + q];
                *reinterpret_cast<float4*>(&Cf[cidx])     = make_float4(v[0], v[1], v[2], v[3]);
                *reinterpret_cast<float4*>(&Cf[cidx + 4]) = make_float4(v[4], v[5], v[6], v[7]);
            }
            __syncwarp();
        }
    }
}

// ---------------- attention: tf32 wmma flash, 64q x 64k, K/V prefetch overlap ----------------
#define APD 68
#define ATTN_SMEM_FLOATS (6*64*APD + 3*64)

__global__ __launch_bounds__(256, 2)
void attn_tc(const float* __restrict__ qb,
             const float* __restrict__ kb,
             const float* __restrict__ vb,
             const float* __restrict__ deltas,
             const float* __restrict__ time_decay,
             float* __restrict__ ob)
{
    extern __shared__ float sm[];
    float* qs  = sm;
    float* ks  = qs  + 64 * APD;
    float* vs  = ks  + 64 * APD;
    float* ps  = vs  + 2 * 64 * APD;
    float* os  = ps  + 64 * APD;
    float* dq_s = os + 64 * APD;
    float* dk_s = dq_s + 64;
    float* l_s  = dk_s + 64;

    int qt = blockIdx.x, h = blockIdx.y, b = blockIdx.z;
    int g = h >> 2;
    int tid = threadIdx.x;
    int wid = tid >> 5;
    float td = time_decay[h];
    float lam = (td > 20.f) ? td : log1pf(__expf(td));
    int q0 = qt * 64;

    {
        #pragma unroll
        for (int p = 0; p < 4; p++) {
            int ch = tid + p * 256;
            int r = ch >> 4, cc = (ch & 15) * 4;
            cp16(&qs[r * APD + cc],
                 qb + ((size_t)(b * SS + q0 + r)) * DD + h * HDIM + cc);
            size_t base = ((size_t)(b * SS + r)) * (GG * HDIM) + g * HDIM + cc;
            cp16(&ks[r * APD + cc], kb + base);
            cp16(&vs[r * APD + cc], vb + base);
        }
        cp_commit();
    }
    if (tid < 64) dq_s[tid] = deltas[b * SS + q0 + tid];
    #pragma unroll
    for (int p = 0; p < 16; p++) {
        int idx = tid + p * 256;
        os[(idx >> 6) * APD + (idx & 63)] = 0.f;
    }

    const float scale = 0.125f;
    int rw = wid & 3;
    int cw = wid >> 2;
    int prow = tid >> 2, psub = tid & 3;
    float m_prev = -INFINITY, l_run = 0.f;
    const int NT = SS / 64;

    for (int kt = 0; kt < NT; kt++) {
        int vbuf = kt & 1;
        if (tid < 64) dk_s[tid] = deltas[b * SS + kt * 64 + tid];
        cp_wait<0>();
        __syncthreads();

        {
            wmma::fragment<wmma::accumulator, 16, 16, 8, float> sacc[2];
            wmma::fill_fragment(sacc[0], 0.f);
            wmma::fill_fragment(sacc[1], 0.f);
            #pragma unroll
            for (int kk = 0; kk < 8; kk++) {
                wmma::fragment<wmma::matrix_a, 16, 16, 8, wmma::precision::tf32, wmma::row_major> af;
                wmma::fragment<wmma::matrix_b, 16, 16, 8, wmma::precision::tf32, wmma::col_major> bf[2];
                wmma::load_matrix_sync(af, &qs[(rw * 16) * APD + kk * 8], APD);
                #pragma unroll
                for (int j = 0; j < 2; j++)
                    wmma::load_matrix_sync(bf[j], &ks[(cw * 32 + j * 16) * APD + kk * 8], APD);
                #pragma unroll
                for (int j = 0; j < 2; j++)
                    wmma::mma_sync(sacc[j], af, bf[j], sacc[j]);
            }
            #pragma unroll
            for (int j = 0; j < 2; j++)
                wmma::store_matrix_sync(&ps[(rw * 16) * APD + cw * 32 + j * 16],
                                        sacc[j], APD, wmma::mem_row_major);
        }
        __syncthreads();

        if (kt + 1 < NT) {
            #pragma unroll
            for (int p = 0; p < 4; p++) {
                int ch = tid + p * 256;
                int r = ch >> 4, cc = (ch & 15) * 4;
                size_t base = ((size_t)(b * SS + (kt + 1) * 64 + r)) * (GG * HDIM) + g * HDIM + cc;
                cp16(&ks[r * APD + cc], kb + base);
                cp16(&vs[(vbuf ^ 1) * 64 * APD + r * APD + cc], vb + base);
            }
        }
        cp_commit();

        {
            float dqv = dq_s[prow];
            float sv[16];
            float mt = -INFINITY;
            #pragma unroll
            for (int j = 0; j < 16; j++) {
                int c = psub * 16 + j;
                float s = ps[prow * APD + c] * scale - lam * fabsf(dqv - dk_s[c]);
                sv[j] = s;
                mt = fmaxf(mt, s);
            }
            mt = fmaxf(mt, __shfl_xor_sync(0xffffffffu, mt, 1));
            mt = fmaxf(mt, __shfl_xor_sync(0xffffffffu, mt, 2));
            float m_new = fmaxf(m_prev, mt);
            float alpha = __expf(m_prev - m_new);
            float sum = 0.f;
            #pragma unroll
            for (int j = 0; j < 16; j++) {
                float p = __expf(sv[j] - m_new);
                ps[prow * APD + psub * 16 + j] = wmma::__float_to_tf32(p);
                sum += p;
            }
            sum += __shfl_xor_sync(0xffffffffu, sum, 1);
            sum += __shfl_xor_sync(0xffffffffu, sum, 2);
            l_run = l_run * alpha + sum;
            m_prev = m_new;
            #pragma unroll
            for (int j = 0; j < 16; j++)
                os[prow * APD + psub * 16 + j] *= alpha;
        }
        __syncthreads();

        {
            wmma::fragment<wmma::accumulator, 16, 16, 8, float> pacc[2];
            #pragma unroll
            for (int j = 0; j < 2; j++)
                wmma::load_matrix_sync(pacc[j], &os[(rw * 16) * APD + cw * 32 + j * 16],
                                       APD, wmma::mem_row_major);
            #pragma unroll
            for (int kk = 0; kk < 8; kk++) {
                wmma::fragment<wmma::matrix_a, 16, 16, 8, wmma::precision::tf32, wmma::row_major> af;
                wmma::fragment<wmma::matrix_b, 16, 16, 8, wmma::precision::tf32, wmma::row_major> bf[2];
                wmma::load_matrix_sync(af, &ps[(rw * 16) * APD + kk * 8], APD);
                #pragma unroll
                for (int j = 0; j < 2; j++)
                    wmma::load_matrix_sync(bf[j], &vs[vbuf * 64 * APD + (kk * 8) * APD + cw * 32 + j * 16], APD);
                #pragma unroll
                for (int j = 0; j < 2; j++)
                    wmma::mma_sync(pacc[j], af, bf[j], pacc[j]);
            }
            #pragma unroll
            for (int j = 0; j < 2; j++)
                wmma::store_matrix_sync(&os[(rw * 16) * APD + cw * 32 + j * 16],
                                        pacc[j], APD, wmma::mem_row_major);
        }
    }
    __syncthreads();
    if (psub == 0) l_s[prow] = l_run;
    __syncthreads();
    #pragma unroll
    for (int p = 0; p < 16; p++) {
        int idx = tid + p * 256;
        int r = idx >> 6, c = idx & 63;
        ob[((size_t)(b * SS + q0 + r)) * DD + h * HDIM + c] =
            wmma::__float_to_tf32(os[r * APD + c] / l_s[r]);
    }
}

// ---------------- router + bucketing ----------------
__global__ void zero_kernel(int* counts) {
    if (threadIdx.x < EE) counts[threadIdx.x] = 0;
}

__global__ void router_kernel(const float* __restrict__ xn2,
                              const float* __restrict__ rw,
                              const float* __restrict__ rb,
                              int* __restrict__ counts,
                              int* __restrict__ te,
                              int* __restrict__ tr,
                              float* __restrict__ tg)
{
    __shared__ float lg[EE];
    int t = blockIdx.x, tid = threadIdx.x;
    int w = tid >> 5, lane = tid & 31;
    const float* xr = xn2 + (size_t)t * DD;
    float p = 0.f;
    for (int d = lane; d < DD; d += 32)
        p += xr[d] * rw[d * EE + w];
    #pragma unroll
    for (int o = 16; o; o >>= 1) p += __shfl_xor_sync(0xffffffffu, p, o);
    if (lane == 0) lg[w] = p + rb[w];
    __syncthreads();
    if (tid == 0) {
        float best = -INFINITY, second = -INFINITY;
        int i0 = 0, i1 = 0;
        #pragma unroll
        for (int e = 0; e < EE; e++) {
            float v = lg[e];
            if (v > best)        { second = best; i1 = i0; best = v; i0 = e; }
            else if (v > second) { second = v; i1 = e; }
        }
        float g0 = 1.0f / (1.0f + expf(second - best));
        float g1 = 1.0f - g0;
        int r0 = atomicAdd(&counts[i0], 1);
        int r1 = atomicAdd(&counts[i1], 1);
        te[t * 2 + 0] = i0; te[t * 2 + 1] = i1;
        tr[t * 2 + 0] = r0; tr[t * 2 + 1] = r1;
        tg[t * 2 + 0] = g0; tg[t * 2 + 1] = g1;
    }
}

__global__ void offs_kernel(const int* __restrict__ counts, int* __restrict__ offs) {
    if (threadIdx.x == 0 && blockIdx.x == 0) {
        int acc = 0;
        for (int e = 0; e < EE; e++) { offs[e] = acc; acc += counts[e]; }
        offs[EE] = acc;
    }
}

__global__ void pack_kernel(const int* __restrict__ te, const int* __restrict__ tr,
                            const int* __restrict__ offs,
                            int* __restrict__ pair, int* __restrict__ slot)
{
    int t = blockIdx.x * blockDim.x + threadIdx.x;
    if (t >= TT) return;
    #pragma unroll
    for (int k2 = 0; k2 < 2; k2++) {
        int e = te[t * 2 + k2];
        int s = offs[e] + tr[t * 2 + k2];
        pair[s] = t;
        slot[t * 2 + k2] = s;
    }
}

__global__ void combine_kernel(const int* __restrict__ slot,
                               const float* __restrict__ tg,
                               const float* __restrict__ ybuf,
                               float* __restrict__ out)
{
    int t = blockIdx.x, tid = threadIdx.x;
    int s0 = slot[t * 2], s1 = slot[t * 2 + 1];
    float g0 = tg[t * 2], g1 = tg[t * 2 + 1];
    const float4* y0 = reinterpret_cast<const float4*>(ybuf + (size_t)s0 * DD);
    const float4* y1 = reinterpret_cast<const float4*>(ybuf + (size_t)s1 * DD);
    float4* op = reinterpret_cast<float4*>(out + (size_t)t * DD);
    float4 a = op[tid], b0 = y0[tid], b1 = y1[tid];
    a.x += g0 * b0.x + g1 * b1.x;
    a.y += g0 * b0.y + g1 * b1.y;
    a.z += g0 * b0.z + g1 * b1.z;
    a.w += g0 * b0.w + g1 * b1.w;
    op[tid] = a;
}

// ---------------- launch ----------------
extern "C" void kernel_launch(void* const* d_in, const int* in_sizes, int n_in,
                              void* d_out, int out_size)
{
    const float* x      = (const float*)d_in[0];
    const float* deltas = (const float*)d_in[1];
    const float* ln1_s  = (const float*)d_in[2];
    const float* ln1_b  = (const float*)d_in[3];
    const float* wq     = (const float*)d_in[4];
    const float* bq     = (const float*)d_in[5];
    const float* wk     = (const float*)d_in[6];
    const float* bk     = (const float*)d_in[7];
    const float* wv     = (const float*)d_in[8];
    const float* bv     = (const float*)d_in[9];
    const float* wo     = (const float*)d_in[10];
    const float* bo     = (const float*)d_in[11];
    const float* tdcy   = (const float*)d_in[12];
    const float* ln2_s  = (const float*)d_in[13];
    const float* ln2_b  = (const float*)d_in[14];
    const float* rw     = (const float*)d_in[15];
    const float* rb     = (const float*)d_in[16];
    const float* w1     = (const float*)d_in[17];
    const float* b1     = (const float*)d_in[18];
    const float* w2     = (const float*)d_in[19];
    const float* b2     = (const float*)d_in[20];
    float* out = (float*)d_out;

    float *p_xn, *p_q, *p_k, *p_v, *p_o, *p_xn2, *p_xn2r, *p_y, *p_tg;
    float *p_wqr, *p_wkr, *p_wvr, *p_wor;
    __nv_bfloat16 *p_hb, *p_w2b;
    int *p_counts, *p_offs, *p_te, *p_tr, *p_pair, *p_slot;
    cudaGetSymbolAddress((void**)&p_xn,  g_xn);
    cudaGetSymbolAddress((void**)&p_q,   g_q);
    cudaGetSymbolAddress((void**)&p_k,   g_k);
    cudaGetSymbolAddress((void**)&p_v,   g_v);
    cudaGetSymbolAddress((void**)&p_o,   g_o);
    cudaGetSymbolAddress((void**)&p_xn2, g_xn2);
    cudaGetSymbolAddress((void**)&p_xn2r, g_xn2r);
    cudaGetSymbolAddress((void**)&p_hb,  g_hb);
    cudaGetSymbolAddress((void**)&p_w2b, g_w2b);
    cudaGetSymbolAddress((void**)&p_y,   g_y);
    cudaGetSymbolAddress((void**)&p_wqr, g_wqr);
    cudaGetSymbolAddress((void**)&p_wkr, g_wkr);
    cudaGetSymbolAddress((void**)&p_wvr, g_wvr);
    cudaGetSymbolAddress((void**)&p_wor, g_wor);
    cudaGetSymbolAddress((void**)&p_counts, g_counts);
    cudaGetSymbolAddress((void**)&p_offs,   g_offs);
    cudaGetSymbolAddress((void**)&p_te,     g_te);
    cudaGetSymbolAddress((void**)&p_tr,     g_tr);
    cudaGetSymbolAddress((void**)&p_tg,     g_tg);
    cudaGetSymbolAddress((void**)&p_pair,   g_pair);
    cudaGetSymbolAddress((void**)&p_slot,   g_slot);

    const int GEMM_SMEM = GEMM_SMEM_FLOATS * (int)sizeof(float);
    const int ATTN_SMEM = ATTN_SMEM_FLOATS * (int)sizeof(float);
    static bool attr_done = false;
    if (!attr_done) {
        cudaFuncSetAttribute(gemm_tc<0, false, false, false, true,  true,  false, false>,
                             cudaFuncAttributeMaxDynamicSharedMemorySize, GEMM_SMEM);
        cudaFuncSetAttribute(gemm_tc<0, true,  false, false, false, false, false, false>,
                             cudaFuncAttributeMaxDynamicSharedMemorySize, GEMM_SMEM);
        cudaFuncSetAttribute(gemm_tc<1, false, true,  true,  false, false, true,  true >,
                             cudaFuncAttributeMaxDynamicSharedMemorySize, GEMM_SMEM);
        cudaFuncSetAttribute(gemm_bf,
                             cudaFuncAttributeMaxDynamicSharedMemorySize, GEMM_BF_SMEM);
        cudaFuncSetAttribute(attn_tc,
                             cudaFuncAttributeMaxDynamicSharedMemorySize, ATTN_SMEM);
        attr_done = true;
    }

    // 0) LN1 (rounded output)
    ln_kernel<1><<<TT, 256>>>(x, ln1_s, ln1_b, p_xn, nullptr);
    // 1-4) pre-round small weights; 5) w2 -> bf16
    f2tf_kernel<<<(DD * DD / 4 + 255) / 256, 256>>>(wq, p_wqr, DD * DD / 4);
    f2tf_kernel<<<(DD * GG * HDIM / 4 + 255) / 256, 256>>>(wk, p_wkr, DD * GG * HDIM / 4);
    f2tf_kernel<<<(DD * GG * HDIM / 4 + 255) / 256, 256>>>(wv, p_wvr, DD * GG * HDIM / 4);
    f2tf_kernel<<<(DD * DD / 4 + 255) / 256, 256>>>(wo, p_wor, DD * DD / 4);
    f2bf_kernel<<<(EE * FF * DD / 4 + 255) / 256, 256>>>(w2, p_w2b, EE * FF * DD / 4);
    // 6) fused Q/K/V projection
    gemm_tc<0, false, false, false, true, true, false, false><<<dim3(12, TT / BM, 1), 256, GEMM_SMEM>>>(
        p_xn, p_wqr, bq, nullptr, p_q, TT, DD, DD, nullptr, nullptr, nullptr, 0, 0,
        p_wkr, bk, p_k, p_wvr, bv, p_v);
    // 7) attention
    attn_tc<<<dim3(SS / 64, HH, BB), 256, ATTN_SMEM>>>(p_q, p_k, p_v, deltas, tdcy, p_o);
    // 8) output projection + residual
    gemm_tc<0, true, false, false, false, false, false, false><<<dim3(DD / BN, TT / BM, 1), 256, GEMM_SMEM>>>(
        p_o, p_wor, bo, x, out, TT, DD, DD, nullptr, nullptr, nullptr, 0, 0,
        nullptr, nullptr, nullptr, nullptr, nullptr, nullptr);
    // 9) LN2 dual
    ln_kernel<2><<<TT, 256>>>(out, ln2_s, ln2_b, p_xn2, p_xn2r);
    // 10) router + bucketing
    zero_kernel<<<1, 32>>>(p_counts);
    router_kernel<<<TT, 256>>>(p_xn2, rw, rb, p_counts, p_te, p_tr, p_tg);
    offs_kernel<<<1, 1>>>(p_counts, p_offs);
    pack_kernel<<<TT / 256, 256>>>(p_te, p_tr, p_offs, p_pair, p_slot);
    // 11) expert GEMM1 (tf32, gathered, gelu, bf16 h out; w1 raw in-frag CVT)
    gemm_tc<1, false, true, true, false, false, true, true><<<dim3(FF / BN, NPAIR / BM, EE), 256, GEMM_SMEM>>>(
        p_xn2r, w1, b1, nullptr, (float*)p_hb, 0, FF, DD, p_pair, p_counts, p_offs,
        (size_t)DD * FF, (size_t)FF,
        nullptr, nullptr, nullptr, nullptr, nullptr, nullptr);
    // 12) expert GEMM2 (bf16 h x bf16 w2 -> fp32 y)
    gemm_bf<<<dim3(DD / BN, NPAIR / BM, EE), 256, GEMM_BF_SMEM>>>(
        p_hb, p_w2b, b2, p_y, DD, FF, p_counts, p_offs,
        (size_t)FF * DD, (size_t)DD);
    // 13) combine
    combine_kernel<<<TT, 256>>>(p_slot, p_tg, p_y, out);

    (void)in_sizes; (void)n_in; (void)out_size;
}

// round 17
// speedup vs baseline: 1.2509x; 1.0029x over previous
#include <cuda_runtime.h>
#include <cuda_bf16.h>
#include <cstdint>
#include <math.h>
#include <mma.h>

using namespace nvcuda;

// ---------------- problem constants ----------------
#define BB   2
#define SS   2048
#define TT   4096          // B*S tokens
#define DD   1024
#define HH   16
#define GG   4
#define HDIM 64
#define EE   8
#define FF   4096
#define NPAIR (TT*2)

// ---------------- scratch ----------------
__device__ float g_xn [TT*DD];           // tf32-rounded
__device__ float g_q  [TT*DD];           // tf32-rounded
__device__ float g_k  [TT*GG*HDIM];      // tf32-rounded
__device__ float g_v  [TT*GG*HDIM];      // tf32-rounded
__device__ float g_o  [TT*DD];           // tf32-rounded
__device__ float g_xn2 [TT*DD];          // exact (router)
__device__ float g_xn2r[TT*DD];          // tf32-rounded (GEMM1 A)
__device__ __nv_bfloat16 g_hb [(size_t)NPAIR*FF];  // 67 MB gelu out (bf16)
__device__ __nv_bfloat16 g_w2b[(size_t)EE*FF*DD];  // 67 MB w2 (bf16)
__device__ float g_y  [(size_t)NPAIR*DD];   // exact
__device__ float g_wqr[DD*DD];
__device__ float g_wkr[DD*GG*HDIM];
__device__ float g_wvr[DD*GG*HDIM];
__device__ float g_wor[DD*DD];
__device__ int   g_counts[EE];
__device__ int   g_offs[EE+1];
__device__ int   g_te [NPAIR];
__device__ int   g_tr [NPAIR];
__device__ float g_tg [NPAIR];
__device__ int   g_pair[NPAIR];
__device__ int   g_slot[NPAIR];

// ---------------- helpers ----------------
__device__ __forceinline__ float tanh_approx(float x) {
    float y;
    asm("tanh.approx.f32 %0, %1;" : "=f"(y) : "f"(x));
    return y;
}
__device__ __forceinline__ float gelu_tanh(float x) {
    const float c0 = 0.7978845608028654f;
    float x3 = x * x * x;
    float t = tanh_approx(c0 * (x + 0.044715f * x3));
    return 0.5f * x * (1.0f + t);
}

template<class Frag>
__device__ __forceinline__ void frag_to_tf32(Frag& f) {
    #pragma unroll
    for (int i = 0; i < f.num_elements; i++)
        f.x[i] = wmma::__float_to_tf32(f.x[i]);
}

__device__ __forceinline__ void cp16(void* s, const void* g) {
    unsigned int sa = (unsigned int)__cvta_generic_to_shared(s);
    asm volatile("cp.async.cg.shared.global [%0], [%1], 16;\n" :: "r"(sa), "l"(g));
}
__device__ __forceinline__ void cp16z(void* s, const void* g, bool v) {
    unsigned int sa = (unsigned int)__cvta_generic_to_shared(s);
    int sz = v ? 16 : 0;
    asm volatile("cp.async.cg.shared.global [%0], [%1], 16, %2;\n" :: "r"(sa), "l"(g), "r"(sz));
}
__device__ __forceinline__ void cp_commit() { asm volatile("cp.async.commit_group;\n"); }
template<int N> __device__ __forceinline__ void cp_wait() {
    asm volatile("cp.async.wait_group %0;\n" :: "n"(N));
}

// ---------------- fp32 -> tf32(RN) rounding pass ----------------
__global__ void f2tf_kernel(const float* __restrict__ in,
                            float* __restrict__ out, int n4)
{
    int i = blockIdx.x * blockDim.x + threadIdx.x;
    if (i >= n4) return;
    float4 v = reinterpret_cast<const float4*>(in)[i];
    v.x = wmma::__float_to_tf32(v.x);
    v.y = wmma::__float_to_tf32(v.y);
    v.z = wmma::__float_to_tf32(v.z);
    v.w = wmma::__float_to_tf32(v.w);
    reinterpret_cast<float4*>(out)[i] = v;
}

// ---------------- fp32 -> bf16 conversion ----------------
__global__ void f2bf_kernel(const float* __restrict__ in,
                            __nv_bfloat16* __restrict__ out, int n4)
{
    int i = blockIdx.x * blockDim.x + threadIdx.x;
    if (i >= n4) return;
    float4 v = reinterpret_cast<const float4*>(in)[i];
    __nv_bfloat162 a = __floats2bfloat162_rn(v.x, v.y);
    __nv_bfloat162 b = __floats2bfloat162_rn(v.z, v.w);
    uint2 u;
    u.x = *reinterpret_cast<unsigned int*>(&a);
    u.y = *reinterpret_cast<unsigned int*>(&b);
    reinterpret_cast<uint2*>(out)[i] = u;
}

// ---------------- LayerNorm. MODE: 0=exact, 1=rounded, 2=dual ----------------
template<int MODE>
__global__ void ln_kernel(const float* __restrict__ x,
                          const float* __restrict__ scale,
                          const float* __restrict__ bias,
                          float* __restrict__ out,
                          float* __restrict__ outr)
{
    __shared__ float red[8];
    int t = blockIdx.x, tid = threadIdx.x;
    const float4* xp = reinterpret_cast<const float4*>(x + (size_t)t * DD);
    float4 v = xp[tid];
    float s = v.x + v.y + v.z + v.w;
    #pragma unroll
    for (int o = 16; o; o >>= 1) s += __shfl_xor_sync(0xffffffffu, s, o);
    if ((tid & 31) == 0) red[tid >> 5] = s;
    __syncthreads();
    if (tid < 8) {
        float r = red[tid];
        #pragma unroll
        for (int o = 4; o; o >>= 1) r += __shfl_xor_sync(0xffu, r, o);
        if (tid == 0) red[0] = r;
    }
    __syncthreads();
    float mu = red[0] * (1.0f / DD);
    float d0 = v.x - mu, d1 = v.y - mu, d2 = v.z - mu, d3 = v.w - mu;
    float sq = d0*d0 + d1*d1 + d2*d2 + d3*d3;
    #pragma unroll
    for (int o = 16; o; o >>= 1) sq += __shfl_xor_sync(0xffffffffu, sq, o);
    __syncthreads();
    if ((tid & 31) == 0) red[tid >> 5] = sq;
    __syncthreads();
    if (tid < 8) {
        float r = red[tid];
        #pragma unroll
        for (int o = 4; o; o >>= 1) r += __shfl_xor_sync(0xffu, r, o);
        if (tid == 0) red[0] = r;
    }
    __syncthreads();
    float rstd = rsqrtf(red[0] * (1.0f / DD) + 1e-6f);
    float4 sc = reinterpret_cast<const float4*>(scale)[tid];
    float4 bi = reinterpret_cast<const float4*>(bias)[tid];
    float4 o4;
    o4.x = d0 * rstd * sc.x + bi.x;
    o4.y = d1 * rstd * sc.y + bi.y;
    o4.z = d2 * rstd * sc.z + bi.z;
    o4.w = d3 * rstd * sc.w + bi.w;
    if (MODE == 1) {
        o4.x = wmma::__float_to_tf32(o4.x);
        o4.y = wmma::__float_to_tf32(o4.y);
        o4.z = wmma::__float_to_tf32(o4.z);
        o4.w = wmma::__float_to_tf32(o4.w);
    }
    reinterpret_cast<float4*>(out + (size_t)t * DD)[tid] = o4;
    if (MODE == 2) {
        float4 r4;
        r4.x = wmma::__float_to_tf32(o4.x);
        r4.y = wmma::__float_to_tf32(o4.y);
        r4.z = wmma::__float_to_tf32(o4.z);
        r4.w = wmma::__float_to_tf32(o4.w);
        reinterpret_cast<float4*>(outr + (size_t)t * DD)[tid] = r4;
    }
}

// ---------------- tf32 GEMM, cp.async double-buffered, 128x128x32 (champion) ----------------
#define BM 128
#define BN 128
#define BKT 32
#define ALD 40
#define BLD 136
#define GEMM_SMEM_FLOATS (2*128*ALD + 2*32*BLD + 8*256)

template<int ACT, bool RESID, bool GATHER, bool SEG, bool QKV, bool ROUT, bool CVTB, bool B16O>
__global__ __launch_bounds__(256, 2)
void gemm_tc(const float* __restrict__ A,
             const float* __restrict__ Bmat,
             const float* __restrict__ biasp,
             const float* __restrict__ resid,
             float* __restrict__ C,
             int M, int N, int Kd,
             const int* __restrict__ gather,
             const int* __restrict__ counts,
             const int* __restrict__ offs,
             size_t strideB, size_t strideBias,
             const float* __restrict__ B2, const float* __restrict__ bias2, float* __restrict__ C2,
             const float* __restrict__ B3, const float* __restrict__ bias3, float* __restrict__ C3)
{
    extern __shared__ float smem[];
    float* As    = smem;
    float* Bs    = As + 2 * 128 * ALD;
    float* stage = Bs + 2 * 32 * BLD;

    int off = 0, Mseg = M, Nn = N, bn;
    const float* Bm = Bmat;
    const float* bias = biasp;
    float* Cout = C;
    if (QKV) {
        int xb = blockIdx.x;
        if (xb < 8)       { bn = xb * 128; }
        else if (xb < 10) { Bm = B2; bias = bias2; Cout = C2; Nn = 256; bn = (xb - 8) * 128; }
        else              { Bm = B3; bias = bias3; Cout = C3; Nn = 256; bn = (xb - 10) * 128; }
    } else {
        bn = blockIdx.x * BN;
    }
    if (SEG) {
        int e = blockIdx.z;
        Mseg = counts[e];
        off  = offs[e];
        Bm   = Bmat + (size_t)e * strideB;
        bias = biasp + (size_t)e * strideBias;
    }
    int bm = blockIdx.y * BM;
    if (bm >= Mseg) return;

    int tid  = threadIdx.x;
    int wid  = tid >> 5;
    int lane = tid & 31;
    int wm   = wid & 3;
    int wn   = wid >> 2;

    int arow = tid >> 3;
    int acol = (tid & 7) * 4;
    const float* aptr[4];
    bool aok[4];
    #pragma unroll
    for (int p = 0; p < 4; p++) {
        int grow = bm + arow + p * 32;
        aok[p] = grow < Mseg;
        long src = 0;
        if (aok[p]) src = GATHER ? (long)gather[off + grow] : (long)(off + grow);
        aptr[p] = A + (size_t)src * Kd + acol;
    }
    int brow = tid >> 3;
    int bcol = (tid & 7) * 4;
    const float* bptr = Bm + (size_t)brow * Nn + bn + bcol;

    wmma::fragment<wmma::accumulator, 16, 16, 8, float> acc[2][4];
    #pragma unroll
    for (int i = 0; i < 2; i++)
        #pragma unroll
        for (int j = 0; j < 4; j++) wmma::fill_fragment(acc[i][j], 0.0f);

    int nk = Kd / BKT;

    {
        #pragma unroll
        for (int p = 0; p < 4; p++)
            cp16z(&As[(0 * 128 + arow + p * 32) * ALD + acol], aptr[p], aok[p]);
        #pragma unroll
        for (int p = 0; p < 4; p++)
            cp16(&Bs[(0 * 32 + brow) * BLD + bcol + p * 32], bptr + p * 32);
        cp_commit();
    }

    for (int it = 0; it < nk; it++) {
        int buf = it & 1;
        if (it + 1 < nk) {
            int k0 = (it + 1) * BKT;
            int nb = buf ^ 1;
            #pragma unroll
            for (int p = 0; p < 4; p++)
                cp16z(&As[(nb * 128 + arow + p * 32) * ALD + acol], aptr[p] + k0, aok[p]);
            #pragma unroll
            for (int p = 0; p < 4; p++)
                cp16(&Bs[(nb * 32 + brow) * BLD + bcol + p * 32],
                     bptr + (size_t)k0 * Nn + p * 32);
        }
        cp_commit();
        cp_wait<1>();
        __syncthreads();

        #pragma unroll
        for (int kk = 0; kk < BKT / 8; kk++) {
            wmma::fragment<wmma::matrix_a, 16, 16, 8, wmma::precision::tf32, wmma::row_major> af[2];
            wmma::fragment<wmma::matrix_b, 16, 16, 8, wmma::precision::tf32, wmma::row_major> bf[4];
            #pragma unroll
            for (int i = 0; i < 2; i++)
                wmma::load_matrix_sync(af[i], &As[(buf * 128 + wm * 32 + i * 16) * ALD + kk * 8], ALD);
            #pragma unroll
            for (int j = 0; j < 4; j++) {
                wmma::load_matrix_sync(bf[j], &Bs[(buf * 32 + kk * 8) * BLD + wn * 64 + j * 16], BLD);
                if (CVTB) frag_to_tf32(bf[j]);
            }
            #pragma unroll
            for (int i = 0; i < 2; i++)
                #pragma unroll
                for (int j = 0; j < 4; j++)
                    wmma::mma_sync(acc[i][j], af[i], bf[j], acc[i][j]);
        }
        __syncthreads();
    }

    int er  = lane >> 1;
    int ec0 = (lane & 1) * 8;
    #pragma unroll
    for (int i = 0; i < 2; i++) {
        #pragma unroll
        for (int j = 0; j < 4; j++) {
            wmma::store_matrix_sync(&stage[wid * 256], acc[i][j], 16, wmma::mem_row_major);
            __syncwarp();
            int grow = bm + wm * 32 + i * 16 + er;
            if (grow < Mseg) {
                int gcol = bn + wn * 64 + j * 16 + ec0;
                size_t cidx = (size_t)(off + grow) * Nn + gcol;
                float v[8];
                #pragma unroll
                for (int q = 0; q < 4; q++) {
                    v[q]     = stage[wid * 256 + er * 16 + ec0 + q]     + bias[gcol + q];
                    v[q + 4] = stage[wid * 256 + er * 16 + ec0 + 4 + q] + bias[gcol + 4 + q];
                }
                if (ACT == 1) {
                    #pragma unroll
                    for (int q = 0; q < 8; q++) v[q] = gelu_tanh(v[q]);
                }
                if (RESID) {
                    float4 r0 = *reinterpret_cast<const float4*>(&resid[cidx]);
                    float4 r1 = *reinterpret_cast<const float4*>(&resid[cidx + 4]);
                    v[0] += r0.x; v[1] += r0.y; v[2] += r0.z; v[3] += r0.w;
                    v[4] += r1.x; v[5] += r1.y; v[6] += r1.z; v[7] += r1.w;
                }
                if (ROUT) {
                    #pragma unroll
                    for (int q = 0; q < 8; q++) v[q] = wmma::__float_to_tf32(v[q]);
                }
                if (B16O) {
                    __nv_bfloat16* Cb = reinterpret_cast<__nv_bfloat16*>(Cout);
                    __nv_bfloat162 h0 = __floats2bfloat162_rn(v[0], v[1]);
                    __nv_bfloat162 h1 = __floats2bfloat162_rn(v[2], v[3]);
                    __nv_bfloat162 h2 = __floats2bfloat162_rn(v[4], v[5]);
                    __nv_bfloat162 h3 = __floats2bfloat162_rn(v[6], v[7]);
                    uint4 u;
                    u.x = *reinterpret_cast<unsigned int*>(&h0);
                    u.y = *reinterpret_cast<unsigned int*>(&h1);
                    u.z = *reinterpret_cast<unsigned int*>(&h2);
                    u.w = *reinterpret_cast<unsigned int*>(&h3);
                    *reinterpret_cast<uint4*>(&Cb[cidx]) = u;
                } else {
                    *reinterpret_cast<float4*>(&Cout[cidx])     = make_float4(v[0], v[1], v[2], v[3]);
                    *reinterpret_cast<float4*>(&Cout[cidx + 4]) = make_float4(v[4], v[5], v[6], v[7]);
                }
            }
            __syncwarp();
        }
    }
}

// ---------------- bf16 GEMM (MoE GEMM2), cp.async double-buffered, 128x128x64 ----------------
#define BKB 64      // bf16 k-tile
#define HALD 72     // bf16 lead dim A (144B rows)
#define HBLD 136    // bf16 lead dim B (272B rows)
#define GEMM_BF_SMEM (2*128*HALD*2 + 2*64*HBLD*2 + 8*256*4)

__global__ __launch_bounds__(256, 2)
void gemm_bf(const __nv_bfloat16* __restrict__ A,
             const __nv_bfloat16* __restrict__ Bmat,
             const float* __restrict__ biasp,
             float* __restrict__ Cf,
             int N, int Kd,
             const int* __restrict__ counts,
             const int* __restrict__ offs,
             size_t strideB, size_t strideBias)
{
    extern __shared__ char smemc[];
    __nv_bfloat16* As = reinterpret_cast<__nv_bfloat16*>(smemc);   // [2][128][HALD]
    __nv_bfloat16* Bs = As + 2 * 128 * HALD;                        // [2][64][HBLD]
    float* stage = reinterpret_cast<float*>(Bs + 2 * 64 * HBLD);

    int e = blockIdx.z;
    int Mseg = counts[e];
    int off  = offs[e];
    const __nv_bfloat16* Bm = Bmat + (size_t)e * strideB;
    const float* bias = biasp + (size_t)e * strideBias;
    int bm = blockIdx.y * BM;
    if (bm >= Mseg) return;
    int bn = blockIdx.x * BN;

    int tid  = threadIdx.x;
    int wid  = tid >> 5;
    int lane = tid & 31;
    int wm   = wid & 3;
    int wn   = wid >> 2;

    // A tile: 128 rows x 64 bf16 (128B/row) = 8 chunks/row, 1024 chunks, 4/thread
    int ar0 = tid >> 3;                // 0..31 (+32 per pass)
    int ach = (tid & 7) * 8;           // bf16 offset (8 bf16 = 16B)
    const __nv_bfloat16* aptr[4];
    bool aok[4];
    #pragma unroll
    for (int p = 0; p < 4; p++) {
        int grow = bm + ar0 + p * 32;
        aok[p] = grow < Mseg;
        long src = aok[p] ? (long)(off + grow) : 0;
        aptr[p] = A + (size_t)src * Kd + ach;
    }
    // B tile: 64 rows x 128 bf16 (256B/row) = 16 chunks/row, 1024 chunks, 4/thread
    int br0 = tid >> 4;                // 0..15 (+16 per pass)
    int bch = (tid & 15) * 8;
    const __nv_bfloat16* bptr = Bm + (size_t)br0 * N + bn + bch;

    wmma::fragment<wmma::accumulator, 16, 16, 16, float> acc[2][4];
    #pragma unroll
    for (int i = 0; i < 2; i++)
        #pragma unroll
        for (int j = 0; j < 4; j++) wmma::fill_fragment(acc[i][j], 0.0f);

    int nk = Kd / BKB;

    {
        #pragma unroll
        for (int p = 0; p < 4; p++)
            cp16z(&As[(0 * 128 + ar0 + p * 32) * HALD + ach], aptr[p], aok[p]);
        #pragma unroll
        for (int p = 0; p < 4; p++)
            cp16(&Bs[(0 * 64 + br0 + p * 16) * HBLD + bch], bptr + (size_t)(p * 16) * N);
        cp_commit();
    }

    for (int it = 0; it < nk; it++) {
        int buf = it & 1;
        if (it + 1 < nk) {
            int k0 = (it + 1) * BKB;
            int nb = buf ^ 1;
            #pragma unroll
            for (int p = 0; p < 4; p++)
                cp16z(&As[(nb * 128 + ar0 + p * 32) * HALD + ach], aptr[p] + k0, aok[p]);
            #pragma unroll
            for (int p = 0; p < 4; p++)
                cp16(&Bs[(nb * 64 + br0 + p * 16) * HBLD + bch],
                     bptr + (size_t)(k0 + p * 16) * N);
        }
        cp_commit();
        cp_wait<1>();
        __syncthreads();

        #pragma unroll
        for (int kk = 0; kk < BKB / 16; kk++) {
            wmma::fragment<wmma::matrix_a, 16, 16, 16, __nv_bfloat16, wmma::row_major> af[2];
            wmma::fragment<wmma::matrix_b, 16, 16, 16, __nv_bfloat16, wmma::row_major> bf[4];
            #pragma unroll
            for (int i = 0; i < 2; i++)
                wmma::load_matrix_sync(af[i], &As[(buf * 128 + wm * 32 + i * 16) * HALD + kk * 16], HALD);
            #pragma unroll
            for (int j = 0; j < 4; j++)
                wmma::load_matrix_sync(bf[j], &Bs[(buf * 64 + kk * 16) * HBLD + wn * 64 + j * 16], HBLD);
            #pragma unroll
            for (int i = 0; i < 2; i++)
                #pragma unroll
                for (int j = 0; j < 4; j++)
                    wmma::mma_sync(acc[i][j], af[i], bf[j], acc[i][j]);
        }
        __syncthreads();
    }

    int er  = lane >> 1;
    int ec0 = (lane & 1) * 8;
    #pragma unroll
    for (int i = 0; i < 2; i++) {
        #pragma unroll
        for (int j = 0; j < 4; j++) {
            wmma::store_matrix_sync(&stage[wid * 256], acc[i][j], 16, wmma::mem_row_major);
            __syncwarp();
            int grow = bm + wm * 32 + i * 16 + er;
            if (grow < Mseg) {
                int gcol = bn + wn * 64 + j * 16 + ec0;
                size_t cidx = (size_t)(off + grow) * N + gcol;
                float v[8];
                #pragma unroll
                for (int q = 0; q < 8; q++)
                    v[q] = stage[wid * 256 + er * 16 + ec0 + q] + bias[gcol + q];
                *reinterpret_cast<float4*>(&Cf[cidx])     = make_float4(v[0], v[1], v[2], v[3]);
                *reinterpret_cast<float4*>(&Cf[cidx + 4]) = make_float4(v[4], v[5], v[6], v[7]);
            }
            __syncwarp();
        }
    }
}

// ---------------- attention: tf32 wmma flash, 64q x 64k, K/V prefetch overlap ----------------
#define APD 68
#define ATTN_SMEM_FLOATS (6*64*APD + 3*64)

__global__ __launch_bounds__(256, 2)
void attn_tc(const float* __restrict__ qb,
             const float* __restrict__ kb,
             const float* __restrict__ vb,
             const float* __restrict__ deltas,
             const float* __restrict__ time_decay,
             float* __restrict__ ob)
{
    extern __shared__ float sm[];
    float* qs  = sm;
    float* ks  = qs  + 64 * APD;
    float* vs  = ks  + 64 * APD;
    float* ps  = vs  + 2 * 64 * APD;
    float* os  = ps  + 64 * APD;
    float* dq_s = os + 64 * APD;
    float* dk_s = dq_s + 64;
    float* l_s  = dk_s + 64;

    int qt = blockIdx.x, h = blockIdx.y, b = blockIdx.z;
    int g = h >> 2;
    int tid = threadIdx.x;
    int wid = tid >> 5;
    float td = time_decay[h];
    float lam = (td > 20.f) ? td : log1pf(__expf(td));
    int q0 = qt * 64;

    {
        #pragma unroll
        for (int p = 0; p < 4; p++) {
            int ch = tid + p * 256;
            int r = ch >> 4, cc = (ch & 15) * 4;
            cp16(&qs[r * APD + cc],
                 qb + ((size_t)(b * SS + q0 + r)) * DD + h * HDIM + cc);
            size_t base = ((size_t)(b * SS + r)) * (GG * HDIM) + g * HDIM + cc;
            cp16(&ks[r * APD + cc], kb + base);
            cp16(&vs[r * APD + cc], vb + base);
        }
        cp_commit();
    }
    if (tid < 64) dq_s[tid] = deltas[b * SS + q0 + tid];
    #pragma unroll
    for (int p = 0; p < 16; p++) {
        int idx = tid + p * 256;
        os[(idx >> 6) * APD + (idx & 63)] = 0.f;
    }

    const float scale = 0.125f;
    int rw = wid & 3;
    int cw = wid >> 2;
    int prow = tid >> 2, psub = tid & 3;
    float m_prev = -INFINITY, l_run = 0.f;
    const int NT = SS / 64;

    for (int kt = 0; kt < NT; kt++) {
        int vbuf = kt & 1;
        if (tid < 64) dk_s[tid] = deltas[b * SS + kt * 64 + tid];
        cp_wait<0>();
        __syncthreads();

        {
            wmma::fragment<wmma::accumulator, 16, 16, 8, float> sacc[2];
            wmma::fill_fragment(sacc[0], 0.f);
            wmma::fill_fragment(sacc[1], 0.f);
            #pragma unroll
            for (int kk = 0; kk < 8; kk++) {
                wmma::fragment<wmma::matrix_a, 16, 16, 8, wmma::precision::tf32, wmma::row_major> af;
                wmma::fragment<wmma::matrix_b, 16, 16, 8, wmma::precision::tf32, wmma::col_major> bf[2];
                wmma::load_matrix_sync(af, &qs[(rw * 16) * APD + kk * 8], APD);
                #pragma unroll
                for (int j = 0; j < 2; j++)
                    wmma::load_matrix_sync(bf[j], &ks[(cw * 32 + j * 16) * APD + kk * 8], APD);
                #pragma unroll
                for (int j = 0; j < 2; j++)
                    wmma::mma_sync(sacc[j], af, bf[j], sacc[j]);
            }
            #pragma unroll
            for (int j = 0; j < 2; j++)
                wmma::store_matrix_sync(&ps[(rw * 16) * APD + cw * 32 + j * 16],
                                        sacc[j], APD, wmma::mem_row_major);
        }
        __syncthreads();

        if (kt + 1 < NT) {
            #pragma unroll
            for (int p = 0; p < 4; p++) {
                int ch = tid + p * 256;
                int r = ch >> 4, cc = (ch & 15) * 4;
                size_t base = ((size_t)(b * SS + (kt + 1) * 64 + r)) * (GG * HDIM) + g * HDIM + cc;
                cp16(&ks[r * APD + cc], kb + base);
                cp16(&vs[(vbuf ^ 1) * 64 * APD + r * APD + cc], vb + base);
            }
        }
        cp_commit();

        {
            float dqv = dq_s[prow];
            float sv[16];
            float mt = -INFINITY;
            #pragma unroll
            for (int j = 0; j < 16; j++) {
                int c = psub * 16 + j;
                float s = ps[prow * APD + c] * scale - lam * fabsf(dqv - dk_s[c]);
                sv[j] = s;
                mt = fmaxf(mt, s);
            }
            mt = fmaxf(mt, __shfl_xor_sync(0xffffffffu, mt, 1));
            mt = fmaxf(mt, __shfl_xor_sync(0xffffffffu, mt, 2));
            float m_new = fmaxf(m_prev, mt);
            float alpha = __expf(m_prev - m_new);
            float sum = 0.f;
            #pragma unroll
            for (int j = 0; j < 16; j++) {
                float p = __expf(sv[j] - m_new);
                ps[prow * APD + psub * 16 + j] = wmma::__float_to_tf32(p);
                sum += p;
            }
            sum += __shfl_xor_sync(0xffffffffu, sum, 1);
            sum += __shfl_xor_sync(0xffffffffu, sum, 2);
            l_run = l_run * alpha + sum;
            m_prev = m_new;
            #pragma unroll
            for (int j = 0; j < 16; j++)
                os[prow * APD + psub * 16 + j] *= alpha;
        }
        __syncthreads();

        {
            wmma::fragment<wmma::accumulator, 16, 16, 8, float> pacc[2];
            #pragma unroll
            for (int j = 0; j < 2; j++)
                wmma::load_matrix_sync(pacc[j], &os[(rw * 16) * APD + cw * 32 + j * 16],
                                       APD, wmma::mem_row_major);
            #pragma unroll
            for (int kk = 0; kk < 8; kk++) {
                wmma::fragment<wmma::matrix_a, 16, 16, 8, wmma::precision::tf32, wmma::row_major> af;
                wmma::fragment<wmma::matrix_b, 16, 16, 8, wmma::precision::tf32, wmma::row_major> bf[2];
                wmma::load_matrix_sync(af, &ps[(rw * 16) * APD + kk * 8], APD);
                #pragma unroll
                for (int j = 0; j < 2; j++)
                    wmma::load_matrix_sync(bf[j], &vs[vbuf * 64 * APD + (kk * 8) * APD + cw * 32 + j * 16], APD);
                #pragma unroll
                for (int j = 0; j < 2; j++)
                    wmma::mma_sync(pacc[j], af, bf[j], pacc[j]);
            }
            #pragma unroll
            for (int j = 0; j < 2; j++)
                wmma::store_matrix_sync(&os[(rw * 16) * APD + cw * 32 + j * 16],
                                        pacc[j], APD, wmma::mem_row_major);
        }
    }
    __syncthreads();
    if (psub == 0) l_s[prow] = l_run;
    __syncthreads();
    #pragma unroll
    for (int p = 0; p < 16; p++) {
        int idx = tid + p * 256;
        int r = idx >> 6, c = idx & 63;
        ob[((size_t)(b * SS + q0 + r)) * DD + h * HDIM + c] =
            wmma::__float_to_tf32(os[r * APD + c] / l_s[r]);
    }
}

// ---------------- router + bucketing ----------------
__global__ void zero_kernel(int* counts) {
    if (threadIdx.x < EE) counts[threadIdx.x] = 0;
}

__global__ void router_kernel(const float* __restrict__ xn2,
                              const float* __restrict__ rw,
                              const float* __restrict__ rb,
                              int* __restrict__ counts,
                              int* __restrict__ te,
                              int* __restrict__ tr,
                              float* __restrict__ tg)
{
    __shared__ float lg[EE];
    int t = blockIdx.x, tid = threadIdx.x;
    int w = tid >> 5, lane = tid & 31;
    const float* xr = xn2 + (size_t)t * DD;
    float p = 0.f;
    for (int d = lane; d < DD; d += 32)
        p += xr[d] * rw[d * EE + w];
    #pragma unroll
    for (int o = 16; o; o >>= 1) p += __shfl_xor_sync(0xffffffffu, p, o);
    if (lane == 0) lg[w] = p + rb[w];
    __syncthreads();
    if (tid == 0) {
        float best = -INFINITY, second = -INFINITY;
        int i0 = 0, i1 = 0;
        #pragma unroll
        for (int e = 0; e < EE; e++) {
            float v = lg[e];
            if (v > best)        { second = best; i1 = i0; best = v; i0 = e; }
            else if (v > second) { second = v; i1 = e; }
        }
        float g0 = 1.0f / (1.0f + expf(second - best));
        float g1 = 1.0f - g0;
        int r0 = atomicAdd(&counts[i0], 1);
        int r1 = atomicAdd(&counts[i1], 1);
        te[t * 2 + 0] = i0; te[t * 2 + 1] = i1;
        tr[t * 2 + 0] = r0; tr[t * 2 + 1] = r1;
        tg[t * 2 + 0] = g0; tg[t * 2 + 1] = g1;
    }
}

__global__ void offs_kernel(const int* __restrict__ counts, int* __restrict__ offs) {
    if (threadIdx.x == 0 && blockIdx.x == 0) {
        int acc = 0;
        for (int e = 0; e < EE; e++) { offs[e] = acc; acc += counts[e]; }
        offs[EE] = acc;
    }
}

__global__ void pack_kernel(const int* __restrict__ te, const int* __restrict__ tr,
                            const int* __restrict__ offs,
                            int* __restrict__ pair, int* __restrict__ slot)
{
    int t = blockIdx.x * blockDim.x + threadIdx.x;
    if (t >= TT) return;
    #pragma unroll
    for (int k2 = 0; k2 < 2; k2++) {
        int e = te[t * 2 + k2];
        int s = offs[e] + tr[t * 2 + k2];
        pair[s] = t;
        slot[t * 2 + k2] = s;
    }
}

__global__ void combine_kernel(const int* __restrict__ slot,
                               const float* __restrict__ tg,
                               const float* __restrict__ ybuf,
                               float* __restrict__ out)
{
    int t = blockIdx.x, tid = threadIdx.x;
    int s0 = slot[t * 2], s1 = slot[t * 2 + 1];
    float g0 = tg[t * 2], g1 = tg[t * 2 + 1];
    const float4* y0 = reinterpret_cast<const float4*>(ybuf + (size_t)s0 * DD);
    const float4* y1 = reinterpret_cast<const float4*>(ybuf + (size_t)s1 * DD);
    float4* op = reinterpret_cast<float4*>(out + (size_t)t * DD);
    float4 a = op[tid], b0 = y0[tid], b1 = y1[tid];
    a.x += g0 * b0.x + g1 * b1.x;
    a.y += g0 * b0.y + g1 * b1.y;
    a.z += g0 * b0.z + g1 * b1.z;
    a.w += g0 * b0.w + g1 * b1.w;
    op[tid] = a;
}

// ---------------- launch ----------------
extern "C" void kernel_launch(void* const* d_in, const int* in_sizes, int n_in,
                              void* d_out, int out_size)
{
    const float* x      = (const float*)d_in[0];
    const float* deltas = (const float*)d_in[1];
    const float* ln1_s  = (const float*)d_in[2];
    const float* ln1_b  = (const float*)d_in[3];
    const float* wq     = (const float*)d_in[4];
    const float* bq     = (const float*)d_in[5];
    const float* wk     = (const float*)d_in[6];
    const float* bk     = (const float*)d_in[7];
    const float* wv     = (const float*)d_in[8];
    const float* bv     = (const float*)d_in[9];
    const float* wo     = (const float*)d_in[10];
    const float* bo     = (const float*)d_in[11];
    const float* tdcy   = (const float*)d_in[12];
    const float* ln2_s  = (const float*)d_in[13];
    const float* ln2_b  = (const float*)d_in[14];
    const float* rw     = (const float*)d_in[15];
    const float* rb     = (const float*)d_in[16];
    const float* w1     = (const float*)d_in[17];
    const float* b1     = (const float*)d_in[18];
    const float* w2     = (const float*)d_in[19];
    const float* b2     = (const float*)d_in[20];
    float* out = (float*)d_out;

    float *p_xn, *p_q, *p_k, *p_v, *p_o, *p_xn2, *p_xn2r, *p_y, *p_tg;
    float *p_wqr, *p_wkr, *p_wvr, *p_wor;
    __nv_bfloat16 *p_hb, *p_w2b;
    int *p_counts, *p_offs, *p_te, *p_tr, *p_pair, *p_slot;
    cudaGetSymbolAddress((void**)&p_xn,  g_xn);
    cudaGetSymbolAddress((void**)&p_q,   g_q);
    cudaGetSymbolAddress((void**)&p_k,   g_k);
    cudaGetSymbolAddress((void**)&p_v,   g_v);
    cudaGetSymbolAddress((void**)&p_o,   g_o);
    cudaGetSymbolAddress((void**)&p_xn2, g_xn2);
    cudaGetSymbolAddress((void**)&p_xn2r, g_xn2r);
    cudaGetSymbolAddress((void**)&p_hb,  g_hb);
    cudaGetSymbolAddress((void**)&p_w2b, g_w2b);
    cudaGetSymbolAddress((void**)&p_y,   g_y);
    cudaGetSymbolAddress((void**)&p_wqr, g_wqr);
    cudaGetSymbolAddress((void**)&p_wkr, g_wkr);
    cudaGetSymbolAddress((void**)&p_wvr, g_wvr);
    cudaGetSymbolAddress((void**)&p_wor, g_wor);
    cudaGetSymbolAddress((void**)&p_counts, g_counts);
    cudaGetSymbolAddress((void**)&p_offs,   g_offs);
    cudaGetSymbolAddress((void**)&p_te,     g_te);
    cudaGetSymbolAddress((void**)&p_tr,     g_tr);
    cudaGetSymbolAddress((void**)&p_tg,     g_tg);
    cudaGetSymbolAddress((void**)&p_pair,   g_pair);
    cudaGetSymbolAddress((void**)&p_slot,   g_slot);

    const int GEMM_SMEM = GEMM_SMEM_FLOATS * (int)sizeof(float);
    const int ATTN_SMEM = ATTN_SMEM_FLOATS * (int)sizeof(float);
    static bool attr_done = false;
    if (!attr_done) {
        cudaFuncSetAttribute(gemm_tc<0, false, false, false, true,  true,  false, false>,
                             cudaFuncAttributeMaxDynamicSharedMemorySize, GEMM_SMEM);
        cudaFuncSetAttribute(gemm_tc<0, true,  false, false, false, false, false, false>,
                             cudaFuncAttributeMaxDynamicSharedMemorySize, GEMM_SMEM);
        cudaFuncSetAttribute(gemm_tc<1, false, true,  true,  false, false, true,  true >,
                             cudaFuncAttributeMaxDynamicSharedMemorySize, GEMM_SMEM);
        cudaFuncSetAttribute(gemm_bf,
                             cudaFuncAttributeMaxDynamicSharedMemorySize, GEMM_BF_SMEM);
        cudaFuncSetAttribute(attn_tc,
                             cudaFuncAttributeMaxDynamicSharedMemorySize, ATTN_SMEM);
        attr_done = true;
    }

    // 0) LN1 (rounded output)
    ln_kernel<1><<<TT, 256>>>(x, ln1_s, ln1_b, p_xn, nullptr);
    // 1-4) pre-round small weights; 5) w2 -> bf16
    f2tf_kernel<<<(DD * DD / 4 + 255) / 256, 256>>>(wq, p_wqr, DD * DD / 4);
    f2tf_kernel<<<(DD * GG * HDIM / 4 + 255) / 256, 256>>>(wk, p_wkr, DD * GG * HDIM / 4);
    f2tf_kernel<<<(DD * GG * HDIM / 4 + 255) / 256, 256>>>(wv, p_wvr, DD * GG * HDIM / 4);
    f2tf_kernel<<<(DD * DD / 4 + 255) / 256, 256>>>(wo, p_wor, DD * DD / 4);
    f2bf_kernel<<<(EE * FF * DD / 4 + 255) / 256, 256>>>(w2, p_w2b, EE * FF * DD / 4);
    // 6) fused Q/K/V projection
    gemm_tc<0, false, false, false, true, true, false, false><<<dim3(12, TT / BM, 1), 256, GEMM_SMEM>>>(
        p_xn, p_wqr, bq, nullptr, p_q, TT, DD, DD, nullptr, nullptr, nullptr, 0, 0,
        p_wkr, bk, p_k, p_wvr, bv, p_v);
    // 7) attention
    attn_tc<<<dim3(SS / 64, HH, BB), 256, ATTN_SMEM>>>(p_q, p_k, p_v, deltas, tdcy, p_o);
    // 8) output projection + residual
    gemm_tc<0, true, false, false, false, false, false, false><<<dim3(DD / BN, TT / BM, 1), 256, GEMM_SMEM>>>(
        p_o, p_wor, bo, x, out, TT, DD, DD, nullptr, nullptr, nullptr, 0, 0,
        nullptr, nullptr, nullptr, nullptr, nullptr, nullptr);
    // 9) LN2 dual
    ln_kernel<2><<<TT, 256>>>(out, ln2_s, ln2_b, p_xn2, p_xn2r);
    // 10) router + bucketing
    zero_kernel<<<1, 32>>>(p_counts);
    router_kernel<<<TT, 256>>>(p_xn2, rw, rb, p_counts, p_te, p_tr, p_tg);
    offs_kernel<<<1, 1>>>(p_counts, p_offs);
    pack_kernel<<<TT / 256, 256>>>(p_te, p_tr, p_offs, p_pair, p_slot);
    // 11) expert GEMM1 (tf32, gathered, gelu, bf16 h out; w1 raw in-frag CVT)
    gemm_tc<1, false, true, true, false, false, true, true><<<dim3(FF / BN, NPAIR / BM, EE), 256, GEMM_SMEM>>>(
        p_xn2r, w1, b1, nullptr, (float*)p_hb, 0, FF, DD, p_pair, p_counts, p_offs,
        (size_t)DD * FF, (size_t)FF,
        nullptr, nullptr, nullptr, nullptr, nullptr, nullptr);
    // 12) expert GEMM2 (bf16 h x bf16 w2 -> fp32 y; BKT=64)
    gemm_bf<<<dim3(DD / BN, NPAIR / BM, EE), 256, GEMM_BF_SMEM>>>(
        p_hb, p_w2b, b2, p_y, DD, FF, p_counts, p_offs,
        (size_t)FF * DD, (size_t)DD);
    // 13) combine
    combine_kernel<<<TT, 256>>>(p_slot, p_tg, p_y, out);

    (void)in_sizes; (void)n_in; (void)out_size;
}